// round 2
// baseline (speedup 1.0000x reference)
#include <cuda_runtime.h>
#include <math.h>

#define BATCH 64
#define SEQ   256
#define EDIM  300
#define HID   512
#define ATTD  256
#define NROWS (BATCH*SEQ)          // 16384

typedef unsigned long long u64;

// ------------------------- scratch (static device memory) -------------------
__device__ float g_e[NROWS*EDIM];              // renormed embeddings  [16384,300]
__device__ float g_xw[2][NROWS*3*HID];         // input projections    [dir][16384,1536]
__device__ float g_h[NROWS*2*HID];             // concat hidden        [b,s,1024]
__device__ float g_state[2][2][HID*BATCH];     // [parity][dir][512][64]  (column-major!)
__device__ float g_target[BATCH*2*HID];        // pooled target        [64,1024]
__device__ float g_tb[BATCH*ATTD];             // target@W1b + b1      [64,256]
__device__ float g_o[NROWS*ATTD];              // tanh attention feats [16384,256]
__device__ float g_alfa[BATCH*ATTD*SEQ];       // beta -> alfa         [64,256,256]
__device__ float g_att[NROWS*2*HID];           // result               [b*256+k,1024]

// ------------------------- f32x2 helpers -------------------------------------
__device__ __forceinline__ u64 dup2(float w) {
    u64 r; asm("mov.b64 %0, {%1, %1};" : "=l"(r) : "f"(w)); return r;
}
__device__ __forceinline__ u64 fma2(u64 a, u64 b, u64 c) {
    u64 d; asm("fma.rn.f32x2 %0, %1, %2, %3;" : "=l"(d) : "l"(a), "l"(b), "l"(c));
    return d;
}
__device__ __forceinline__ float2 unpack2(u64 v) {
    float2 f; asm("mov.b64 {%0, %1}, %2;" : "=f"(f.x), "=f"(f.y) : "l"(v)); return f;
}
__device__ __forceinline__ u64 zero2() { return 0ull; }

__device__ __forceinline__ float warp_sum(float v) {
    #pragma unroll
    for (int o = 16; o > 0; o >>= 1) v += __shfl_xor_sync(0xffffffffu, v, o);
    return v;
}
__device__ __forceinline__ float warp_max(float v) {
    #pragma unroll
    for (int o = 16; o > 0; o >>= 1) v = fmaxf(v, __shfl_xor_sync(0xffffffffu, v, o));
    return v;
}

// ------------------------- K0: zero GRU state --------------------------------
__global__ void k_zero_state() {
    int i = blockIdx.x * blockDim.x + threadIdx.x;
    if (i < 2*2*HID*BATCH) ((float*)g_state)[i] = 0.f;
}

// ------------------------- K1: embedding gather + renorm ---------------------
__global__ void k_embed(const int* __restrict__ x, const float* __restrict__ emb) {
    int w = blockIdx.x * (blockDim.x >> 5) + (threadIdx.x >> 5);
    int lane = threadIdx.x & 31;
    if (w >= NROWS) return;
    const float* src = emb + (long)x[w] * EDIM;
    float v[10];
    float ss = 0.f;
    #pragma unroll
    for (int i = 0; i < 10; i++) {
        int c = lane + 32*i;
        float t = (c < EDIM) ? __ldg(src + c) : 0.f;
        v[i] = t; ss += t*t;
    }
    ss = warp_sum(ss);
    float sc = fminf(1.f, 5.f / (sqrtf(ss) + 1e-7f));
    float* dst = g_e + (long)w * EDIM;
    #pragma unroll
    for (int i = 0; i < 10; i++) {
        int c = lane + 32*i;
        if (c < EDIM) dst[c] = v[i] * sc;
    }
}

// ------------------------- generic fp32 tiled GEMMs (f32x2 core) -------------
// C[M,N] = A[M,K] . B[N,K]^T   (NT), 64x64 tile, 256 thr
// epi: 0 -> C = acc + bias[col]
//      1 -> C = tanh(acc + tb2[(row>>8)*256 + col])
//      2 -> C = acc
__global__ __launch_bounds__(256) void k_gemm_nt(
    const float* __restrict__ A, const float* __restrict__ B, float* __restrict__ C,
    int M, int N, int K, int lda, int ldb, int ldc,
    long sA, long sB, long sC,
    const float* __restrict__ bias, const float* __restrict__ tb2, int epi)
{
    __shared__ __align__(16) float As[16][64];
    __shared__ __align__(16) float Bs[16][64];
    int bz = blockIdx.z;
    A += sA * bz; B += sB * bz; C += sC * bz;
    int m0 = blockIdx.x << 6, n0 = blockIdx.y << 6;
    int tid = threadIdx.x;
    int tx = tid & 15, ty = tid >> 4;
    u64 acc[4][2];
    #pragma unroll
    for (int i = 0; i < 4; i++) { acc[i][0] = 0ull; acc[i][1] = 0ull; }
    for (int k0 = 0; k0 < K; k0 += 16) {
        int r = tid >> 2;
        int cb = (tid & 3) << 2;
        #pragma unroll
        for (int p = 0; p < 4; p++) {
            int c = cb + p;
            float va = 0.f, vb = 0.f;
            if (k0 + c < K) {
                va = A[(long)(m0 + r) * lda + k0 + c];
                vb = B[(long)(n0 + r) * ldb + k0 + c];
            }
            As[c][r] = va;
            Bs[c][r] = vb;
        }
        __syncthreads();
        #pragma unroll
        for (int k = 0; k < 16; k++) {
            float4 av = *(const float4*)&As[k][ty << 2];
            ulonglong2 bv = *(const ulonglong2*)&Bs[k][tx << 2];
            u64 a0 = dup2(av.x), a1 = dup2(av.y), a2 = dup2(av.z), a3 = dup2(av.w);
            acc[0][0] = fma2(a0, bv.x, acc[0][0]);
            acc[0][1] = fma2(a0, bv.y, acc[0][1]);
            acc[1][0] = fma2(a1, bv.x, acc[1][0]);
            acc[1][1] = fma2(a1, bv.y, acc[1][1]);
            acc[2][0] = fma2(a2, bv.x, acc[2][0]);
            acc[2][1] = fma2(a2, bv.y, acc[2][1]);
            acc[3][0] = fma2(a3, bv.x, acc[3][0]);
            acc[3][1] = fma2(a3, bv.y, acc[3][1]);
        }
        __syncthreads();
    }
    #pragma unroll
    for (int i = 0; i < 4; i++) {
        int row = m0 + (ty << 2) + i;
        float vv[4];
        float2 p0 = unpack2(acc[i][0]);
        float2 p1 = unpack2(acc[i][1]);
        vv[0] = p0.x; vv[1] = p0.y; vv[2] = p1.x; vv[3] = p1.y;
        #pragma unroll
        for (int j = 0; j < 4; j++) {
            int col = n0 + (tx << 2) + j;
            float v = vv[j];
            if (epi == 0)      v += bias[col];
            else if (epi == 1) v = tanhf(v + tb2[((row >> 8) << 8) + col]);
            C[(long)row * ldc + col] = v;
        }
    }
}

// C[M,N] = A[M,K] . B[K,N]   (NN), 64x64 tile, 256 thr, plain epilogue
__global__ __launch_bounds__(256) void k_gemm_nn(
    const float* __restrict__ A, const float* __restrict__ B, float* __restrict__ C,
    int M, int N, int K, int lda, int ldb, int ldc,
    long sA, long sB, long sC)
{
    __shared__ __align__(16) float As[16][64];
    __shared__ __align__(16) float Bs[16][64];
    int bz = blockIdx.z;
    A += sA * bz; B += sB * bz; C += sC * bz;
    int m0 = blockIdx.x << 6, n0 = blockIdx.y << 6;
    int tid = threadIdx.x;
    int tx = tid & 15, ty = tid >> 4;
    u64 acc[4][2];
    #pragma unroll
    for (int i = 0; i < 4; i++) { acc[i][0] = 0ull; acc[i][1] = 0ull; }
    for (int k0 = 0; k0 < K; k0 += 16) {
        {   // A tile (transposed store)
            int r = tid >> 2;
            int cb = (tid & 3) << 2;
            #pragma unroll
            for (int p = 0; p < 4; p++) {
                int c = cb + p;
                float va = 0.f;
                if (k0 + c < K) va = A[(long)(m0 + r) * lda + k0 + c];
                As[c][r] = va;
            }
        }
        {   // B tile (direct)
            int kk = tid >> 4;
            int cb = (tid & 15) << 2;
            #pragma unroll
            for (int p = 0; p < 4; p++) {
                int c = cb + p;
                float vb = 0.f;
                if (k0 + kk < K) vb = B[(long)(k0 + kk) * ldb + n0 + c];
                Bs[kk][c] = vb;
            }
        }
        __syncthreads();
        #pragma unroll
        for (int k = 0; k < 16; k++) {
            float4 av = *(const float4*)&As[k][ty << 2];
            ulonglong2 bv = *(const ulonglong2*)&Bs[k][tx << 2];
            u64 a0 = dup2(av.x), a1 = dup2(av.y), a2 = dup2(av.z), a3 = dup2(av.w);
            acc[0][0] = fma2(a0, bv.x, acc[0][0]);
            acc[0][1] = fma2(a0, bv.y, acc[0][1]);
            acc[1][0] = fma2(a1, bv.x, acc[1][0]);
            acc[1][1] = fma2(a1, bv.y, acc[1][1]);
            acc[2][0] = fma2(a2, bv.x, acc[2][0]);
            acc[2][1] = fma2(a2, bv.y, acc[2][1]);
            acc[3][0] = fma2(a3, bv.x, acc[3][0]);
            acc[3][1] = fma2(a3, bv.y, acc[3][1]);
        }
        __syncthreads();
    }
    #pragma unroll
    for (int i = 0; i < 4; i++) {
        int row = m0 + (ty << 2) + i;
        float2 p0 = unpack2(acc[i][0]);
        float2 p1 = unpack2(acc[i][1]);
        float vv[4] = {p0.x, p0.y, p1.x, p1.y};
        #pragma unroll
        for (int j = 0; j < 4; j++) {
            int col = n0 + (tx << 2) + j;
            C[(long)row * ldc + col] = vv[j];
        }
    }
}

// ------------------------- K4: fused GRU step v2 -----------------------------
// 128 blocks = 2 dirs x 64 j-tiles (8 units each), 128 threads.
// Thread = (j local 0..7, 4 batch rows). State is column-major [512][64] so the
// h tile stages to smem k-major with a straight coalesced copy. Inner loop per
// k: 1 LDS.128 (4 batch, packed f32x2 pairs) + 3 scalar W loads + 6 FFMA2.
#define WPITCH 68
__global__ __launch_bounds__(128) void k_gru_step(
    const float* __restrict__ Wf, const float* __restrict__ Wb,
    const float* __restrict__ bf, const float* __restrict__ bb, int t)
{
    __shared__ __align__(16) float Hs[64*64];        // [k][m]
    __shared__ __align__(16) float Ws[24*WPITCH];    // [gate*8+j][k]

    int blk = blockIdx.x;
    int dir = blk >> 6;
    int j0  = (blk & 63) << 3;
    int tid = threadIdx.x;
    int j   = tid & 7;
    int mg  = tid >> 3;                 // 0..15
    int m0  = mg << 2;

    const float* W  = dir ? Wb : Wf;
    const float* bh = dir ? bb : bf;
    const float* hp = g_state[t & 1][dir];
    float*       hn = g_state[(t + 1) & 1][dir];

    u64 ar01 = 0, ar23 = 0, az01 = 0, az23 = 0, an01 = 0, an23 = 0;

    for (int k0 = 0; k0 < HID; k0 += 64) {
        // stage H: contiguous 4096 floats (column-major state => k-major tile)
        const float4* hsrc = (const float4*)(hp + (long)k0 * 64);
        float4* hdst = (float4*)Hs;
        #pragma unroll
        for (int p = 0; p < 8; p++) hdst[tid + (p << 7)] = hsrc[tid + (p << 7)];
        // stage W: 24 rows x 16 float4
        #pragma unroll
        for (int p = 0; p < 3; p++) {
            int l = tid + (p << 7);
            if (l < 384) {
                int r  = l >> 4;
                int c4 = l & 15;
                int wrow = ((r >> 3) << 9) + j0 + (r & 7);
                *(float4*)&Ws[r * WPITCH + (c4 << 2)] =
                    *(const float4*)&W[(long)wrow * HID + k0 + (c4 << 2)];
            }
        }
        __syncthreads();
        #pragma unroll 8
        for (int k = 0; k < 64; k++) {
            ulonglong2 h = *(const ulonglong2*)&Hs[(k << 6) + m0];
            u64 wr = dup2(Ws[j * WPITCH + k]);
            u64 wz = dup2(Ws[(8 + j) * WPITCH + k]);
            u64 wn = dup2(Ws[(16 + j) * WPITCH + k]);
            ar01 = fma2(wr, h.x, ar01);
            ar23 = fma2(wr, h.y, ar23);
            az01 = fma2(wz, h.x, az01);
            az23 = fma2(wz, h.y, az23);
            an01 = fma2(wn, h.x, an01);
            an23 = fma2(wn, h.y, an23);
        }
        __syncthreads();
    }

    int jg = j0 + j;
    int tt = dir ? (SEQ - 1 - t) : t;
    float br = bh[jg], bz = bh[HID + jg], bn = bh[2 * HID + jg];
    float2 arL = unpack2(ar01), arH = unpack2(ar23);
    float2 azL = unpack2(az01), azH = unpack2(az23);
    float2 anL = unpack2(an01), anH = unpack2(an23);
    float gar[4] = {arL.x, arL.y, arH.x, arH.y};
    float gaz[4] = {azL.x, azL.y, azH.x, azH.y};
    float gan[4] = {anL.x, anL.y, anH.x, anH.y};
    float4 hprev = *(const float4*)&hp[jg * 64 + m0];
    float hpv[4] = {hprev.x, hprev.y, hprev.z, hprev.w};
    float hv[4];
    #pragma unroll
    for (int q = 0; q < 4; q++) {
        int m = m0 + q;
        long row = (long)m * SEQ + tt;
        const float* xwrow = g_xw[dir] + row * (3 * HID);
        float r = 1.f / (1.f + expf(-(xwrow[jg] + gar[q] + br)));
        float z = 1.f / (1.f + expf(-(xwrow[HID + jg] + gaz[q] + bz)));
        float n = tanhf(xwrow[2 * HID + jg] + r * (gan[q] + bn));
        hv[q] = (1.f - z) * n + z * hpv[q];
        g_h[row * (2 * HID) + dir * HID + jg] = hv[q];
    }
    *(float4*)&hn[jg * 64 + m0] = make_float4(hv[0], hv[1], hv[2], hv[3]);
}

// ------------------------- K5: masked mean pooling ---------------------------
__global__ void k_pool(const int* __restrict__ ts, const int* __restrict__ te) {
    int b = blockIdx.x;
    int s0 = ts[b], s1 = te[b];
    float inv = 1.f / (float)(s1 - s0 + 1);
    for (int c = threadIdx.x; c < 2 * HID; c += blockDim.x) {
        float a = 0.f;
        for (int s = s0; s <= s1; s++)
            a += g_h[((long)b * SEQ + s) * (2 * HID) + c];
        g_target[b * 2 * HID + c] = a * inv;
    }
}

// ------------------------- K8b: row softmax over S ---------------------------
__global__ void k_softmax() {
    int row = blockIdx.x * (blockDim.x >> 5) + (threadIdx.x >> 5);
    int lane = threadIdx.x & 31;
    float* p = g_alfa + (long)row * SEQ;
    float v[8];
    float mx = -1e30f;
    #pragma unroll
    for (int i = 0; i < 8; i++) { v[i] = p[lane + 32 * i]; mx = fmaxf(mx, v[i]); }
    mx = warp_max(mx);
    float s = 0.f;
    #pragma unroll
    for (int i = 0; i < 8; i++) { v[i] = expf(v[i] - mx); s += v[i]; }
    s = warp_sum(s);
    float inv = 1.f / s;
    #pragma unroll
    for (int i = 0; i < 8; i++) p[lane + 32 * i] = v[i] * inv;
}

// ------------------------- K10: result @ W2^T + b2 ---------------------------
__global__ void k_final(const float* __restrict__ W2, const float* __restrict__ b2,
                        float* __restrict__ out) {
    int row = blockIdx.x * 8 + (threadIdx.x >> 5);
    int lane = threadIdx.x & 31;
    const float* R = g_att + (long)row * (2 * HID);
    float a0 = 0.f, a1 = 0.f, a2 = 0.f;
    for (int h = lane; h < 2 * HID; h += 32) {
        float r = R[h];
        a0 = fmaf(r, W2[h],            a0);
        a1 = fmaf(r, W2[2 * HID + h],  a1);
        a2 = fmaf(r, W2[4 * HID + h],  a2);
    }
    a0 = warp_sum(a0); a1 = warp_sum(a1); a2 = warp_sum(a2);
    if (lane == 0) {
        out[row * 3 + 0] = a0 + b2[0];
        out[row * 3 + 1] = a1 + b2[1];
        out[row * 3 + 2] = a2 + b2[2];
    }
}

// ------------------------- launcher ------------------------------------------
extern "C" void kernel_launch(void* const* d_in, const int* in_sizes, int n_in,
                              void* d_out, int out_size) {
    const int*   x      = (const int*)  d_in[0];
    const int*   tstart = (const int*)  d_in[1];
    const int*   tend   = (const int*)  d_in[2];
    const float* emb    = (const float*)d_in[3];
    const float* Wih_f  = (const float*)d_in[4];
    const float* Whh_f  = (const float*)d_in[5];
    const float* bih_f  = (const float*)d_in[6];
    const float* bhh_f  = (const float*)d_in[7];
    const float* Wih_b  = (const float*)d_in[8];
    const float* Whh_b  = (const float*)d_in[9];
    const float* bih_b  = (const float*)d_in[10];
    const float* bhh_b  = (const float*)d_in[11];
    const float* W1     = (const float*)d_in[12];
    const float* b1     = (const float*)d_in[13];
    const float* u      = (const float*)d_in[14];
    const float* W2     = (const float*)d_in[15];
    const float* b2     = (const float*)d_in[16];
    float* out = (float*)d_out;

    float *p_e, *p_xw, *p_h, *p_target, *p_tb, *p_o, *p_alfa, *p_att;
    cudaGetSymbolAddress((void**)&p_e,      g_e);
    cudaGetSymbolAddress((void**)&p_xw,     g_xw);
    cudaGetSymbolAddress((void**)&p_h,      g_h);
    cudaGetSymbolAddress((void**)&p_target, g_target);
    cudaGetSymbolAddress((void**)&p_tb,     g_tb);
    cudaGetSymbolAddress((void**)&p_o,      g_o);
    cudaGetSymbolAddress((void**)&p_alfa,   g_alfa);
    cudaGetSymbolAddress((void**)&p_att,    g_att);
    float* p_xw0 = p_xw;
    float* p_xw1 = p_xw + (long)NROWS * 3 * HID;

    k_zero_state<<<512, 256>>>();
    k_embed<<<2048, 256>>>(x, emb);

    // input projections: [16384,300] x [1536,300]^T (+bih)
    k_gemm_nt<<<dim3(256, 24, 1), 256>>>(p_e, Wih_f, p_xw0, NROWS, 3 * HID, EDIM,
                                         EDIM, EDIM, 3 * HID, 0, 0, 0,
                                         bih_f, nullptr, 0);
    k_gemm_nt<<<dim3(256, 24, 1), 256>>>(p_e, Wih_b, p_xw1, NROWS, 3 * HID, EDIM,
                                         EDIM, EDIM, 3 * HID, 0, 0, 0,
                                         bih_b, nullptr, 0);

    // recurrence: 256 fused steps, both directions per launch
    for (int t = 0; t < SEQ; t++)
        k_gru_step<<<128, 128>>>(Whh_f, Whh_b, bhh_f, bhh_b, t);

    // masked mean pool over target span
    k_pool<<<64, 256>>>(tstart, tend);

    // tb[b,a] = target[b] . W1[:,1024:]^T + b1   (M=64,N=256,K=1024)
    k_gemm_nt<<<dim3(1, 4, 1), 256>>>(p_target, W1 + 1024, p_tb, 64, ATTD, 2 * HID,
                                      2 * HID, 4 * HID, ATTD, 0, 0, 0,
                                      b1, nullptr, 0);

    // o = tanh(h . W1[:, :1024]^T + tb[b])       (M=16384,N=256,K=1024)
    k_gemm_nt<<<dim3(256, 4, 1), 256>>>(p_h, W1, p_o, NROWS, ATTD, 2 * HID,
                                        2 * HID, 4 * HID, ATTD, 0, 0, 0,
                                        nullptr, p_tb, 1);

    // beta[b,k,s] = u[k] . o[b,s]                (batched NT, M=N=K=256)
    k_gemm_nt<<<dim3(4, 4, 64), 256>>>(u, p_o, p_alfa, ATTD, SEQ, ATTD,
                                       ATTD, ATTD, SEQ,
                                       0, (long)SEQ * ATTD, (long)ATTD * SEQ,
                                       nullptr, nullptr, 2);

    // softmax over s
    k_softmax<<<2048, 256>>>();

    // result[b,k,:] = alfa[b,k,:] . h[b]         (batched NN, 256x1024x256)
    k_gemm_nn<<<dim3(4, 16, 64), 256>>>(p_alfa, p_h, p_att, ATTD, 2 * HID, SEQ,
                                        SEQ, 2 * HID, 2 * HID,
                                        (long)ATTD * SEQ, (long)SEQ * 2 * HID,
                                        (long)ATTD * 2 * HID);

    // final projection to 3 labels
    k_final<<<2048, 256>>>(W2, b2, out);
}

// round 3
// speedup vs baseline: 1.0451x; 1.0451x over previous
#include <cuda_runtime.h>
#include <math.h>

#define BATCH 64
#define SEQ   256
#define EDIM  300
#define HID   512
#define ATTD  256
#define NROWS (BATCH*SEQ)          // 16384
#define GRU_BLOCKS 128

typedef unsigned long long u64;

// ------------------------- scratch (static device memory) -------------------
__device__ float g_e[NROWS*EDIM];              // renormed embeddings  [16384,300]
__device__ float g_xw[2][NROWS*3*HID];         // input projections    [dir][16384,1536]
__device__ float g_h[NROWS*2*HID];             // concat hidden        [b,s,1024]
// state in interleaved quads: [parity][dir][k2*32+mg] = {h(2k2,2mg),h(2k2,2mg+1),h(2k2+1,2mg),h(2k2+1,2mg+1)}
__device__ float g_state[2][2][HID*BATCH];
__device__ float g_target[BATCH*2*HID];        // pooled target        [64,1024]
__device__ float g_tb[BATCH*ATTD];             // target@W1b + b1      [64,256]
__device__ float g_o[NROWS*ATTD];              // tanh attention feats [16384,256]
__device__ float g_alfa[BATCH*ATTD*SEQ];       // beta -> alfa         [64,256,256]
__device__ float g_att[NROWS*2*HID];           // result               [b*256+k,1024]

__device__ volatile unsigned g_bar_gen;
__device__ unsigned g_bar_cnt;

// ------------------------- f32x2 helpers -------------------------------------
__device__ __forceinline__ u64 dup2(float w) {
    u64 r; asm("mov.b64 %0, {%1, %1};" : "=l"(r) : "f"(w)); return r;
}
__device__ __forceinline__ u64 fma2(u64 a, u64 b, u64 c) {
    u64 d; asm("fma.rn.f32x2 %0, %1, %2, %3;" : "=l"(d) : "l"(a), "l"(b), "l"(c));
    return d;
}
__device__ __forceinline__ float2 unpack2(u64 v) {
    float2 f; asm("mov.b64 {%0, %1}, %2;" : "=f"(f.x), "=f"(f.y) : "l"(v)); return f;
}

__device__ __forceinline__ float warp_sum(float v) {
    #pragma unroll
    for (int o = 16; o > 0; o >>= 1) v += __shfl_xor_sync(0xffffffffu, v, o);
    return v;
}
__device__ __forceinline__ float warp_max(float v) {
    #pragma unroll
    for (int o = 16; o > 0; o >>= 1) v = fmaxf(v, __shfl_xor_sync(0xffffffffu, v, o));
    return v;
}

// ------------------------- K0: zero GRU state + barrier ----------------------
__global__ void k_zero_state() {
    int i = blockIdx.x * blockDim.x + threadIdx.x;
    if (i < 2*2*HID*BATCH) ((float*)g_state)[i] = 0.f;
    if (i == 0) { g_bar_gen = 0u; g_bar_cnt = 0u; }
}

// ------------------------- K1: embedding gather + renorm ---------------------
__global__ void k_embed(const int* __restrict__ x, const float* __restrict__ emb) {
    int w = blockIdx.x * (blockDim.x >> 5) + (threadIdx.x >> 5);
    int lane = threadIdx.x & 31;
    if (w >= NROWS) return;
    const float* src = emb + (long)x[w] * EDIM;
    float v[10];
    float ss = 0.f;
    #pragma unroll
    for (int i = 0; i < 10; i++) {
        int c = lane + 32*i;
        float t = (c < EDIM) ? __ldg(src + c) : 0.f;
        v[i] = t; ss += t*t;
    }
    ss = warp_sum(ss);
    float sc = fminf(1.f, 5.f / (sqrtf(ss) + 1e-7f));
    float* dst = g_e + (long)w * EDIM;
    #pragma unroll
    for (int i = 0; i < 10; i++) {
        int c = lane + 32*i;
        if (c < EDIM) dst[c] = v[i] * sc;
    }
}

// ------------------------- generic fp32 tiled GEMMs (f32x2 core) -------------
// C[M,N] = A[M,K] . B[N,K]^T   (NT), 64x64 tile, 256 thr
__global__ __launch_bounds__(256) void k_gemm_nt(
    const float* __restrict__ A, const float* __restrict__ B, float* __restrict__ C,
    int M, int N, int K, int lda, int ldb, int ldc,
    long sA, long sB, long sC,
    const float* __restrict__ bias, const float* __restrict__ tb2, int epi)
{
    __shared__ __align__(16) float As[16][64];
    __shared__ __align__(16) float Bs[16][64];
    int bz = blockIdx.z;
    A += sA * bz; B += sB * bz; C += sC * bz;
    int m0 = blockIdx.x << 6, n0 = blockIdx.y << 6;
    int tid = threadIdx.x;
    int tx = tid & 15, ty = tid >> 4;
    u64 acc[4][2];
    #pragma unroll
    for (int i = 0; i < 4; i++) { acc[i][0] = 0ull; acc[i][1] = 0ull; }
    for (int k0 = 0; k0 < K; k0 += 16) {
        int r = tid >> 2;
        int cb = (tid & 3) << 2;
        #pragma unroll
        for (int p = 0; p < 4; p++) {
            int c = cb + p;
            float va = 0.f, vb = 0.f;
            if (k0 + c < K) {
                va = A[(long)(m0 + r) * lda + k0 + c];
                vb = B[(long)(n0 + r) * ldb + k0 + c];
            }
            As[c][r] = va;
            Bs[c][r] = vb;
        }
        __syncthreads();
        #pragma unroll
        for (int k = 0; k < 16; k++) {
            float4 av = *(const float4*)&As[k][ty << 2];
            ulonglong2 bv = *(const ulonglong2*)&Bs[k][tx << 2];
            u64 a0 = dup2(av.x), a1 = dup2(av.y), a2 = dup2(av.z), a3 = dup2(av.w);
            acc[0][0] = fma2(a0, bv.x, acc[0][0]);
            acc[0][1] = fma2(a0, bv.y, acc[0][1]);
            acc[1][0] = fma2(a1, bv.x, acc[1][0]);
            acc[1][1] = fma2(a1, bv.y, acc[1][1]);
            acc[2][0] = fma2(a2, bv.x, acc[2][0]);
            acc[2][1] = fma2(a2, bv.y, acc[2][1]);
            acc[3][0] = fma2(a3, bv.x, acc[3][0]);
            acc[3][1] = fma2(a3, bv.y, acc[3][1]);
        }
        __syncthreads();
    }
    #pragma unroll
    for (int i = 0; i < 4; i++) {
        int row = m0 + (ty << 2) + i;
        float vv[4];
        float2 p0 = unpack2(acc[i][0]);
        float2 p1 = unpack2(acc[i][1]);
        vv[0] = p0.x; vv[1] = p0.y; vv[2] = p1.x; vv[3] = p1.y;
        #pragma unroll
        for (int j = 0; j < 4; j++) {
            int col = n0 + (tx << 2) + j;
            float v = vv[j];
            if (epi == 0)      v += bias[col];
            else if (epi == 1) v = tanhf(v + tb2[((row >> 8) << 8) + col]);
            C[(long)row * ldc + col] = v;
        }
    }
}

// C[M,N] = A[M,K] . B[K,N]   (NN), 64x64 tile, 256 thr
__global__ __launch_bounds__(256) void k_gemm_nn(
    const float* __restrict__ A, const float* __restrict__ B, float* __restrict__ C,
    int M, int N, int K, int lda, int ldb, int ldc,
    long sA, long sB, long sC)
{
    __shared__ __align__(16) float As[16][64];
    __shared__ __align__(16) float Bs[16][64];
    int bz = blockIdx.z;
    A += sA * bz; B += sB * bz; C += sC * bz;
    int m0 = blockIdx.x << 6, n0 = blockIdx.y << 6;
    int tid = threadIdx.x;
    int tx = tid & 15, ty = tid >> 4;
    u64 acc[4][2];
    #pragma unroll
    for (int i = 0; i < 4; i++) { acc[i][0] = 0ull; acc[i][1] = 0ull; }
    for (int k0 = 0; k0 < K; k0 += 16) {
        {
            int r = tid >> 2;
            int cb = (tid & 3) << 2;
            #pragma unroll
            for (int p = 0; p < 4; p++) {
                int c = cb + p;
                float va = 0.f;
                if (k0 + c < K) va = A[(long)(m0 + r) * lda + k0 + c];
                As[c][r] = va;
            }
        }
        {
            int kk = tid >> 4;
            int cb = (tid & 15) << 2;
            #pragma unroll
            for (int p = 0; p < 4; p++) {
                int c = cb + p;
                float vb = 0.f;
                if (k0 + kk < K) vb = B[(long)(k0 + kk) * ldb + n0 + c];
                Bs[kk][c] = vb;
            }
        }
        __syncthreads();
        #pragma unroll
        for (int k = 0; k < 16; k++) {
            float4 av = *(const float4*)&As[k][ty << 2];
            ulonglong2 bv = *(const ulonglong2*)&Bs[k][tx << 2];
            u64 a0 = dup2(av.x), a1 = dup2(av.y), a2 = dup2(av.z), a3 = dup2(av.w);
            acc[0][0] = fma2(a0, bv.x, acc[0][0]);
            acc[0][1] = fma2(a0, bv.y, acc[0][1]);
            acc[1][0] = fma2(a1, bv.x, acc[1][0]);
            acc[1][1] = fma2(a1, bv.y, acc[1][1]);
            acc[2][0] = fma2(a2, bv.x, acc[2][0]);
            acc[2][1] = fma2(a2, bv.y, acc[2][1]);
            acc[3][0] = fma2(a3, bv.x, acc[3][0]);
            acc[3][1] = fma2(a3, bv.y, acc[3][1]);
        }
        __syncthreads();
    }
    #pragma unroll
    for (int i = 0; i < 4; i++) {
        int row = m0 + (ty << 2) + i;
        float2 p0 = unpack2(acc[i][0]);
        float2 p1 = unpack2(acc[i][1]);
        float vv[4] = {p0.x, p0.y, p1.x, p1.y};
        #pragma unroll
        for (int j = 0; j < 4; j++) {
            int col = n0 + (tx << 2) + j;
            C[(long)row * ldc + col] = vv[j];
        }
    }
}

// ------------------------- K4: persistent GRU --------------------------------
// 128 blocks = 2 dirs x 64 j-tiles (8 units). 256 threads = j(0..7) x mg(0..31),
// each thread: batch pair (2mg, 2mg+1), 3 gate accumulators (even/odd k split).
// Whh slice lives in smem for the whole kernel, duplicated+interleaved:
//   Wq[k2*24 + gate*8 + j] = {w(2k2),w(2k2),w(2k2+1),w(2k2+1)}
// h state staged per 64-k chunk as quads (straight float4 copy).
#define WQ_QUADS (24*256)           // 6144 float4 = 96KB
#define HQ_QUADS (32*32)            // 1024 float4 = 16KB
#define GRU_SMEM ((WQ_QUADS + HQ_QUADS) * 16)

__global__ __launch_bounds__(256, 1) void k_gru_persistent(
    const float* __restrict__ Wf, const float* __restrict__ Wb,
    const float* __restrict__ bf, const float* __restrict__ bb)
{
    extern __shared__ __align__(16) float smem[];
    ulonglong2* Wq2 = (ulonglong2*)smem;
    ulonglong2* Hq2 = (ulonglong2*)(smem + WQ_QUADS * 4);
    float4*     Hq4 = (float4*)Hq2;

    int blk = blockIdx.x;
    int dir = blk >> 6;
    int j0  = (blk & 63) << 3;
    int tid = threadIdx.x;
    int j   = tid & 7;
    int mg  = tid >> 3;                 // 0..31

    const float* W  = dir ? Wb : Wf;
    const float* bh = dir ? bb : bf;

    // --- one-time: stage W slice (dup'd + 2k-interleaved) ---
    for (int i = tid; i < 24 * 256; i += 256) {
        int r  = i >> 8;                // gate-row 0..23
        int k2 = i & 255;
        int grow = ((r >> 3) << 9) + j0 + (r & 7);
        float2 w = *(const float2*)&W[(long)grow * HID + (k2 << 1)];
        float4 q; q.x = w.x; q.y = w.x; q.z = w.y; q.w = w.y;
        ((float4*)Wq2)[k2 * 24 + r] = q;
    }

    int jg = j0 + j;
    float br = __ldg(&bh[jg]);
    float bz = __ldg(&bh[HID + jg]);
    float bn = __ldg(&bh[2 * HID + jg]);

    int m0 = mg << 1;
    long xw_base0 = ((long)m0 * SEQ) * (3 * HID);
    long xw_base1 = ((long)(m0 + 1) * SEQ) * (3 * HID);
    const float* xw = g_xw[dir];
    int state_quad = ((jg >> 1) << 5) + mg;     // quad index for this thread's output
    int half = (jg & 1);

    for (int t = 0; t < SEQ; t++) {
        const float* sp = g_state[t & 1][dir];
        float*       sn = g_state[(t + 1) & 1][dir];
        int tt = dir ? (SEQ - 1 - t) : t;

        // prefetch gate inputs (hide DRAM latency behind the matmul)
        long xo0 = xw_base0 + (long)tt * (3 * HID);
        long xo1 = xw_base1 + (long)tt * (3 * HID);
        float xr0 = __ldg(&xw[xo0 + jg]);
        float xz0 = __ldg(&xw[xo0 + HID + jg]);
        float xn0 = __ldg(&xw[xo0 + 2 * HID + jg]);
        float xr1 = __ldg(&xw[xo1 + jg]);
        float xz1 = __ldg(&xw[xo1 + HID + jg]);
        float xn1 = __ldg(&xw[xo1 + 2 * HID + jg]);
        // previous state for the leak term (L2, bypass L1 - parity reuse!)
        float2 hpv = __ldg((const float2*)sp + state_quad * 2 + half);
        // (note: __ldg may cache in L1; the parity buffer was last touched 2 steps
        //  ago by THIS kernel, so force L2 with inline cg load instead)
        asm("ld.global.cg.v2.f32 {%0, %1}, [%2];"
            : "=f"(hpv.x), "=f"(hpv.y)
            : "l"((const float2*)sp + state_quad * 2 + half));

        u64 are = 0, aro = 0, aze = 0, azo = 0, ane = 0, ano = 0;

        #pragma unroll 1
        for (int chunk = 0; chunk < 8; chunk++) {
            // stage 64 k of state: 1024 float4, straight copy, L2 (bypass L1)
            __syncthreads();
            const float4* src = (const float4*)sp + (chunk << 10);
            #pragma unroll
            for (int p = 0; p < 4; p++) {
                float4 v;
                asm("ld.global.cg.v4.f32 {%0, %1, %2, %3}, [%4];"
                    : "=f"(v.x), "=f"(v.y), "=f"(v.z), "=f"(v.w)
                    : "l"(src + tid + (p << 8)));
                Hq4[tid + (p << 8)] = v;
            }
            __syncthreads();

            int kq0 = chunk << 5;
            #pragma unroll 4
            for (int k2 = 0; k2 < 32; k2++) {
                ulonglong2 h  = Hq2[(k2 << 5) + mg];
                int wi = (kq0 + k2) * 24 + j;
                ulonglong2 wr = Wq2[wi];
                ulonglong2 wz = Wq2[wi + 8];
                ulonglong2 wn = Wq2[wi + 16];
                are = fma2(wr.x, h.x, are);
                aze = fma2(wz.x, h.x, aze);
                ane = fma2(wn.x, h.x, ane);
                aro = fma2(wr.y, h.y, aro);
                azo = fma2(wz.y, h.y, azo);
                ano = fma2(wn.y, h.y, ano);
            }
        }

        float2 ar = unpack2(are), ar2 = unpack2(aro);
        float2 az = unpack2(aze), az2 = unpack2(azo);
        float2 an = unpack2(ane), an2 = unpack2(ano);
        float gr0 = ar.x + ar2.x + br, gr1 = ar.y + ar2.y + br;
        float gz0 = az.x + az2.x + bz, gz1 = az.y + az2.y + bz;
        float gn0 = an.x + an2.x + bn, gn1 = an.y + an2.y + bn;

        float r0 = 1.f / (1.f + expf(-(xr0 + gr0)));
        float z0 = 1.f / (1.f + expf(-(xz0 + gz0)));
        float n0 = tanhf(xn0 + r0 * gn0);
        float h0 = (1.f - z0) * n0 + z0 * hpv.x;
        float r1 = 1.f / (1.f + expf(-(xr1 + gr1)));
        float z1 = 1.f / (1.f + expf(-(xz1 + gz1)));
        float n1 = tanhf(xn1 + r1 * gn1);
        float h1 = (1.f - z1) * n1 + z1 * hpv.y;

        ((float2*)sn)[state_quad * 2 + half] = make_float2(h0, h1);
        long hrow0 = ((long)m0 * SEQ + tt) * (2 * HID) + dir * HID + jg;
        long hrow1 = ((long)(m0 + 1) * SEQ + tt) * (2 * HID) + dir * HID + jg;
        g_h[hrow0] = h0;
        g_h[hrow1] = h1;

        // ---- grid barrier (skip after last step) ----
        if (t < SEQ - 1) {
            __syncthreads();
            if (tid == 0) {
                __threadfence();
                unsigned a = atomicAdd(&g_bar_cnt, 1u);
                if (a == GRU_BLOCKS - 1) {
                    g_bar_cnt = 0u;
                    __threadfence();
                    g_bar_gen = (unsigned)(t + 1);
                } else {
                    while (g_bar_gen < (unsigned)(t + 1)) { }
                }
            }
            __syncthreads();
        }
    }
}

// ------------------------- K5: masked mean pooling ---------------------------
__global__ void k_pool(const int* __restrict__ ts, const int* __restrict__ te) {
    int b = blockIdx.x;
    int s0 = ts[b], s1 = te[b];
    float inv = 1.f / (float)(s1 - s0 + 1);
    for (int c = threadIdx.x; c < 2 * HID; c += blockDim.x) {
        float a = 0.f;
        for (int s = s0; s <= s1; s++)
            a += g_h[((long)b * SEQ + s) * (2 * HID) + c];
        g_target[b * 2 * HID + c] = a * inv;
    }
}

// ------------------------- K8b: row softmax over S ---------------------------
__global__ void k_softmax() {
    int row = blockIdx.x * (blockDim.x >> 5) + (threadIdx.x >> 5);
    int lane = threadIdx.x & 31;
    float* p = g_alfa + (long)row * SEQ;
    float v[8];
    float mx = -1e30f;
    #pragma unroll
    for (int i = 0; i < 8; i++) { v[i] = p[lane + 32 * i]; mx = fmaxf(mx, v[i]); }
    mx = warp_max(mx);
    float s = 0.f;
    #pragma unroll
    for (int i = 0; i < 8; i++) { v[i] = expf(v[i] - mx); s += v[i]; }
    s = warp_sum(s);
    float inv = 1.f / s;
    #pragma unroll
    for (int i = 0; i < 8; i++) p[lane + 32 * i] = v[i] * inv;
}

// ------------------------- K10: result @ W2^T + b2 ---------------------------
__global__ void k_final(const float* __restrict__ W2, const float* __restrict__ b2,
                        float* __restrict__ out) {
    int row = blockIdx.x * 8 + (threadIdx.x >> 5);
    int lane = threadIdx.x & 31;
    const float* R = g_att + (long)row * (2 * HID);
    float a0 = 0.f, a1 = 0.f, a2 = 0.f;
    for (int h = lane; h < 2 * HID; h += 32) {
        float r = R[h];
        a0 = fmaf(r, W2[h],            a0);
        a1 = fmaf(r, W2[2 * HID + h],  a1);
        a2 = fmaf(r, W2[4 * HID + h],  a2);
    }
    a0 = warp_sum(a0); a1 = warp_sum(a1); a2 = warp_sum(a2);
    if (lane == 0) {
        out[row * 3 + 0] = a0 + b2[0];
        out[row * 3 + 1] = a1 + b2[1];
        out[row * 3 + 2] = a2 + b2[2];
    }
}

// ------------------------- launcher ------------------------------------------
extern "C" void kernel_launch(void* const* d_in, const int* in_sizes, int n_in,
                              void* d_out, int out_size) {
    const int*   x      = (const int*)  d_in[0];
    const int*   tstart = (const int*)  d_in[1];
    const int*   tend   = (const int*)  d_in[2];
    const float* emb    = (const float*)d_in[3];
    const float* Wih_f  = (const float*)d_in[4];
    const float* Whh_f  = (const float*)d_in[5];
    const float* bih_f  = (const float*)d_in[6];
    const float* bhh_f  = (const float*)d_in[7];
    const float* Wih_b  = (const float*)d_in[8];
    const float* Whh_b  = (const float*)d_in[9];
    const float* bih_b  = (const float*)d_in[10];
    const float* bhh_b  = (const float*)d_in[11];
    const float* W1     = (const float*)d_in[12];
    const float* b1     = (const float*)d_in[13];
    const float* u      = (const float*)d_in[14];
    const float* W2     = (const float*)d_in[15];
    const float* b2     = (const float*)d_in[16];
    float* out = (float*)d_out;

    static int smem_set = 0;
    if (!smem_set) {
        cudaFuncSetAttribute(k_gru_persistent,
                             cudaFuncAttributeMaxDynamicSharedMemorySize, GRU_SMEM);
        smem_set = 1;
    }

    float *p_e, *p_xw, *p_h, *p_target, *p_tb, *p_o, *p_alfa, *p_att;
    cudaGetSymbolAddress((void**)&p_e,      g_e);
    cudaGetSymbolAddress((void**)&p_xw,     g_xw);
    cudaGetSymbolAddress((void**)&p_h,      g_h);
    cudaGetSymbolAddress((void**)&p_target, g_target);
    cudaGetSymbolAddress((void**)&p_tb,     g_tb);
    cudaGetSymbolAddress((void**)&p_o,      g_o);
    cudaGetSymbolAddress((void**)&p_alfa,   g_alfa);
    cudaGetSymbolAddress((void**)&p_att,    g_att);
    float* p_xw0 = p_xw;
    float* p_xw1 = p_xw + (long)NROWS * 3 * HID;

    k_zero_state<<<512, 256>>>();
    k_embed<<<2048, 256>>>(x, emb);

    // input projections: [16384,300] x [1536,300]^T (+bih)
    k_gemm_nt<<<dim3(256, 24, 1), 256>>>(p_e, Wih_f, p_xw0, NROWS, 3 * HID, EDIM,
                                         EDIM, EDIM, 3 * HID, 0, 0, 0,
                                         bih_f, nullptr, 0);
    k_gemm_nt<<<dim3(256, 24, 1), 256>>>(p_e, Wih_b, p_xw1, NROWS, 3 * HID, EDIM,
                                         EDIM, EDIM, 3 * HID, 0, 0, 0,
                                         bih_b, nullptr, 0);

    // full recurrence in ONE persistent kernel
    k_gru_persistent<<<GRU_BLOCKS, 256, GRU_SMEM>>>(Whh_f, Whh_b, bhh_f, bhh_b);

    // masked mean pool over target span
    k_pool<<<64, 256>>>(tstart, tend);

    // tb[b,a] = target[b] . W1[:,1024:]^T + b1   (M=64,N=256,K=1024)
    k_gemm_nt<<<dim3(1, 4, 1), 256>>>(p_target, W1 + 1024, p_tb, 64, ATTD, 2 * HID,
                                      2 * HID, 4 * HID, ATTD, 0, 0, 0,
                                      b1, nullptr, 0);

    // o = tanh(h . W1[:, :1024]^T + tb[b])       (M=16384,N=256,K=1024)
    k_gemm_nt<<<dim3(256, 4, 1), 256>>>(p_h, W1, p_o, NROWS, ATTD, 2 * HID,
                                        2 * HID, 4 * HID, ATTD, 0, 0, 0,
                                        nullptr, p_tb, 1);

    // beta[b,k,s] = u[k] . o[b,s]                (batched NT, M=N=K=256)
    k_gemm_nt<<<dim3(4, 4, 64), 256>>>(u, p_o, p_alfa, ATTD, SEQ, ATTD,
                                       ATTD, ATTD, SEQ,
                                       0, (long)SEQ * ATTD, (long)ATTD * SEQ,
                                       nullptr, nullptr, 2);

    // softmax over s
    k_softmax<<<2048, 256>>>();

    // result[b,k,:] = alfa[b,k,:] . h[b]         (batched NN, 256x1024x256)
    k_gemm_nn<<<dim3(4, 16, 64), 256>>>(p_alfa, p_h, p_att, ATTD, 2 * HID, SEQ,
                                        SEQ, 2 * HID, 2 * HID,
                                        (long)ATTD * SEQ, (long)SEQ * 2 * HID,
                                        (long)ATTD * 2 * HID);

    // final projection to 3 labels
    k_final<<<2048, 256>>>(W2, b2, out);
}

// round 5
// speedup vs baseline: 1.4305x; 1.3688x over previous
#include <cuda_runtime.h>
#include <math.h>

#define BATCH 64
#define SEQ   256
#define EDIM  300
#define HID   512
#define ATTD  256
#define NROWS (BATCH*SEQ)          // 16384
#define GRU_BLOCKS 128

typedef unsigned long long u64;

// ------------------------- scratch (static device memory) -------------------
__device__ float g_e[NROWS*EDIM];              // renormed embeddings  [16384,300]
__device__ float g_xw[2][NROWS*3*HID];         // input projections    [dir][b*256+s][1536]
__device__ float g_h[NROWS*2*HID];             // concat hidden        [b,s,1024]
// state quads: [parity][dir][k2*128 + bg*4 + bp*2 + kp]  (k=2*k2+kp, b=2*bg+bp)
__device__ float g_state[2][2][HID*BATCH];
__device__ float g_target[BATCH*2*HID];        // pooled target        [64,1024]
__device__ float g_tbp[8][BATCH*ATTD];         // split-K partials
__device__ float g_tb[BATCH*ATTD];             // target@W1b + b1      [64,256]
__device__ float g_o[NROWS*ATTD];              // tanh attention feats [16384,256]
__device__ float g_alfa[BATCH*ATTD*SEQ];       // beta -> alfa         [64,256,256]
__device__ float g_att[NROWS*2*HID];           // result               [b*256+k,1024]

__device__ volatile unsigned g_bar_gen;
__device__ unsigned g_bar_cnt;

// ------------------------- helpers -------------------------------------------
__device__ __forceinline__ u64 dup2(float w) {
    u64 r; asm("mov.b64 %0, {%1, %1};" : "=l"(r) : "f"(w)); return r;
}
__device__ __forceinline__ u64 fma2(u64 a, u64 b, u64 c) {
    u64 d; asm("fma.rn.f32x2 %0, %1, %2, %3;" : "=l"(d) : "l"(a), "l"(b), "l"(c));
    return d;
}
__device__ __forceinline__ float2 unpack2(u64 v) {
    float2 f; asm("mov.b64 {%0, %1}, %2;" : "=f"(f.x), "=f"(f.y) : "l"(v)); return f;
}
__device__ __forceinline__ void ldg_cg_2x64(const float* p, u64& a, u64& b) {
    asm("ld.global.cg.v2.u64 {%0, %1}, [%2];" : "=l"(a), "=l"(b) : "l"(p));
}
__device__ __forceinline__ float warp_sum(float v) {
    #pragma unroll
    for (int o = 16; o > 0; o >>= 1) v += __shfl_xor_sync(0xffffffffu, v, o);
    return v;
}
__device__ __forceinline__ float warp_max(float v) {
    #pragma unroll
    for (int o = 16; o > 0; o >>= 1) v = fmaxf(v, __shfl_xor_sync(0xffffffffu, v, o));
    return v;
}

// ------------------------- K0: zero GRU state + barrier ----------------------
__global__ void k_zero_state() {
    int i = blockIdx.x * blockDim.x + threadIdx.x;
    if (i < 2*2*HID*BATCH) ((float*)g_state)[i] = 0.f;
    if (i == 0) { g_bar_gen = 0u; g_bar_cnt = 0u; }
}

// ------------------------- K1: embedding gather + renorm ---------------------
__global__ void k_embed(const int* __restrict__ x, const float* __restrict__ emb) {
    int w = blockIdx.x * (blockDim.x >> 5) + (threadIdx.x >> 5);
    int lane = threadIdx.x & 31;
    if (w >= NROWS) return;
    const float* src = emb + (long)x[w] * EDIM;
    float v[10];
    float ss = 0.f;
    #pragma unroll
    for (int i = 0; i < 10; i++) {
        int c = lane + 32*i;
        float t = (c < EDIM) ? __ldg(src + c) : 0.f;
        v[i] = t; ss += t*t;
    }
    ss = warp_sum(ss);
    float sc = fminf(1.f, 5.f / (sqrtf(ss) + 1e-7f));
    float* dst = g_e + (long)w * EDIM;
    #pragma unroll
    for (int i = 0; i < 10; i++) {
        int c = lane + 32*i;
        if (c < EDIM) dst[c] = v[i] * sc;
    }
}

// ------------------------- K2: 128x128 FFMA2 GEMMs ---------------------------
// thread: 8 m-rows x 8 n-cols (4 packed f32x2 col-pairs)
#define GP 132
// NT: C[M,N] = A[M,K] . B[N,K]^T ; epi 0:+bias, 1:tanh(acc+tb2[(row>>8)*256+col]), 2:none
__global__ __launch_bounds__(256) void k_gemm_nt(
    const float* __restrict__ A, const float* __restrict__ B, float* __restrict__ C,
    int K, int lda, int ldb, int ldc, long sA, long sB, long sC,
    const float* __restrict__ bias, const float* __restrict__ tb2, int epi)
{
    __shared__ __align__(16) float As[16*GP];
    __shared__ __align__(16) float Bs[16*GP];
    int bz = blockIdx.z;
    A += sA * bz; B += sB * bz; C += sC * bz;
    int m0 = blockIdx.x << 7, n0 = blockIdx.y << 7;
    int tid = threadIdx.x;
    int tx = tid & 15, ty = tid >> 4;
    int srow = tid >> 1, skh = (tid & 1) << 3;
    const float* Ap = A + (long)(m0 + srow) * lda;
    const float* Bp = B + (long)(n0 + srow) * ldb;
    u64 acc[8][4] = {};
    for (int k0 = 0; k0 < K; k0 += 16) {
        if (k0 + 16 <= K) {
            float4 a0 = *(const float4*)(Ap + k0 + skh);
            float4 a1 = *(const float4*)(Ap + k0 + skh + 4);
            float4 b0 = *(const float4*)(Bp + k0 + skh);
            float4 b1 = *(const float4*)(Bp + k0 + skh + 4);
            As[(skh+0)*GP + srow] = a0.x; As[(skh+1)*GP + srow] = a0.y;
            As[(skh+2)*GP + srow] = a0.z; As[(skh+3)*GP + srow] = a0.w;
            As[(skh+4)*GP + srow] = a1.x; As[(skh+5)*GP + srow] = a1.y;
            As[(skh+6)*GP + srow] = a1.z; As[(skh+7)*GP + srow] = a1.w;
            Bs[(skh+0)*GP + srow] = b0.x; Bs[(skh+1)*GP + srow] = b0.y;
            Bs[(skh+2)*GP + srow] = b0.z; Bs[(skh+3)*GP + srow] = b0.w;
            Bs[(skh+4)*GP + srow] = b1.x; Bs[(skh+5)*GP + srow] = b1.y;
            Bs[(skh+6)*GP + srow] = b1.z; Bs[(skh+7)*GP + srow] = b1.w;
        } else {
            #pragma unroll
            for (int c = 0; c < 8; c++) {
                int kk = k0 + skh + c;
                As[(skh+c)*GP + srow] = (kk < K) ? Ap[kk] : 0.f;
                Bs[(skh+c)*GP + srow] = (kk < K) ? Bp[kk] : 0.f;
            }
        }
        __syncthreads();
        #pragma unroll
        for (int k = 0; k < 16; k++) {
            float a[8]; u64 bq[4];
            *(float4*)&a[0] = *(const float4*)&As[k*GP + (ty<<3)];
            *(float4*)&a[4] = *(const float4*)&As[k*GP + (ty<<3) + 4];
            ulonglong2 t0 = *(const ulonglong2*)&Bs[k*GP + (tx<<3)];
            ulonglong2 t1 = *(const ulonglong2*)&Bs[k*GP + (tx<<3) + 4];
            bq[0] = t0.x; bq[1] = t0.y; bq[2] = t1.x; bq[3] = t1.y;
            #pragma unroll
            for (int i = 0; i < 8; i++) {
                u64 ad = dup2(a[i]);
                acc[i][0] = fma2(ad, bq[0], acc[i][0]);
                acc[i][1] = fma2(ad, bq[1], acc[i][1]);
                acc[i][2] = fma2(ad, bq[2], acc[i][2]);
                acc[i][3] = fma2(ad, bq[3], acc[i][3]);
            }
        }
        __syncthreads();
    }
    #pragma unroll
    for (int i = 0; i < 8; i++) {
        int row = m0 + (ty << 3) + i;
        float v[8];
        #pragma unroll
        for (int p = 0; p < 4; p++) {
            float2 u = unpack2(acc[i][p]);
            v[2*p] = u.x; v[2*p+1] = u.y;
        }
        #pragma unroll
        for (int j = 0; j < 8; j++) {
            int col = n0 + (tx << 3) + j;
            if (epi == 0)      v[j] += bias[col];
            else if (epi == 1) v[j] = tanhf(v[j] + tb2[((row >> 8) << 8) + col]);
        }
        float* cp = C + (long)row * ldc + n0 + (tx << 3);
        *(float4*)cp       = make_float4(v[0], v[1], v[2], v[3]);
        *(float4*)(cp + 4) = make_float4(v[4], v[5], v[6], v[7]);
    }
}

// NN: C[M,N] = A[M,K] . B[K,N]  (K multiple of 16)
__global__ __launch_bounds__(256) void k_gemm_nn(
    const float* __restrict__ A, const float* __restrict__ B, float* __restrict__ C,
    int K, int lda, int ldb, int ldc, long sA, long sB, long sC)
{
    __shared__ __align__(16) float As[16*GP];
    __shared__ __align__(16) float Bs[16*GP];
    int bz = blockIdx.z;
    A += sA * bz; B += sB * bz; C += sC * bz;
    int m0 = blockIdx.x << 7, n0 = blockIdx.y << 7;
    int tid = threadIdx.x;
    int tx = tid & 15, ty = tid >> 4;
    int srow = tid >> 1, skh = (tid & 1) << 3;
    int bkk = tid >> 4, bc8 = (tid & 15) << 3;
    const float* Ap = A + (long)(m0 + srow) * lda;
    u64 acc[8][4] = {};
    for (int k0 = 0; k0 < K; k0 += 16) {
        {
            float4 a0 = *(const float4*)(Ap + k0 + skh);
            float4 a1 = *(const float4*)(Ap + k0 + skh + 4);
            As[(skh+0)*GP + srow] = a0.x; As[(skh+1)*GP + srow] = a0.y;
            As[(skh+2)*GP + srow] = a0.z; As[(skh+3)*GP + srow] = a0.w;
            As[(skh+4)*GP + srow] = a1.x; As[(skh+5)*GP + srow] = a1.y;
            As[(skh+6)*GP + srow] = a1.z; As[(skh+7)*GP + srow] = a1.w;
            const float* bp = B + (long)(k0 + bkk) * ldb + n0 + bc8;
            float4 b0 = *(const float4*)bp;
            float4 b1 = *(const float4*)(bp + 4);
            *(float4*)&Bs[bkk*GP + bc8]     = b0;
            *(float4*)&Bs[bkk*GP + bc8 + 4] = b1;
        }
        __syncthreads();
        #pragma unroll
        for (int k = 0; k < 16; k++) {
            float a[8]; u64 bq[4];
            *(float4*)&a[0] = *(const float4*)&As[k*GP + (ty<<3)];
            *(float4*)&a[4] = *(const float4*)&As[k*GP + (ty<<3) + 4];
            ulonglong2 t0 = *(const ulonglong2*)&Bs[k*GP + (tx<<3)];
            ulonglong2 t1 = *(const ulonglong2*)&Bs[k*GP + (tx<<3) + 4];
            bq[0] = t0.x; bq[1] = t0.y; bq[2] = t1.x; bq[3] = t1.y;
            #pragma unroll
            for (int i = 0; i < 8; i++) {
                u64 ad = dup2(a[i]);
                acc[i][0] = fma2(ad, bq[0], acc[i][0]);
                acc[i][1] = fma2(ad, bq[1], acc[i][1]);
                acc[i][2] = fma2(ad, bq[2], acc[i][2]);
                acc[i][3] = fma2(ad, bq[3], acc[i][3]);
            }
        }
        __syncthreads();
    }
    #pragma unroll
    for (int i = 0; i < 8; i++) {
        int row = m0 + (ty << 3) + i;
        float v[8];
        #pragma unroll
        for (int p = 0; p < 4; p++) {
            float2 u = unpack2(acc[i][p]);
            v[2*p] = u.x; v[2*p+1] = u.y;
        }
        float* cp = C + (long)row * ldc + n0 + (tx << 3);
        *(float4*)cp       = make_float4(v[0], v[1], v[2], v[3]);
        *(float4*)(cp + 4) = make_float4(v[4], v[5], v[6], v[7]);
    }
}

// ------------------------- K3: small split-K NT for target -------------------
// grid (1,4,8): z = K-chunk of 128; C = g_tbp[z]
__global__ __launch_bounds__(256) void k_gemm_target(
    const float* __restrict__ A, const float* __restrict__ B)
{
    __shared__ __align__(16) float As[16][64];
    __shared__ __align__(16) float Bs[16][64];
    int z = blockIdx.z;
    A += z * 128;      // lda 1024
    B += z * 128;      // ldb 2048
    float* C = g_tbp[z];
    int n0 = blockIdx.y << 6;
    int tid = threadIdx.x;
    int tx = tid & 15, ty = tid >> 4;
    float acc[4][4] = {};
    for (int k0 = 0; k0 < 128; k0 += 16) {
        int r = tid >> 2;
        int cb = (tid & 3) << 2;
        #pragma unroll
        for (int p = 0; p < 4; p++) {
            int c = cb + p;
            As[c][r] = A[(long)r * (2*HID) + k0 + c];
            Bs[c][r] = B[(long)(n0 + r) * (4*HID) + k0 + c];
        }
        __syncthreads();
        #pragma unroll
        for (int k = 0; k < 16; k++) {
            float4 av = *(const float4*)&As[k][ty << 2];
            float4 bv = *(const float4*)&Bs[k][tx << 2];
            float a[4] = {av.x, av.y, av.z, av.w};
            float b[4] = {bv.x, bv.y, bv.z, bv.w};
            #pragma unroll
            for (int i = 0; i < 4; i++)
                #pragma unroll
                for (int j = 0; j < 4; j++)
                    acc[i][j] = fmaf(a[i], b[j], acc[i][j]);
        }
        __syncthreads();
    }
    #pragma unroll
    for (int i = 0; i < 4; i++) {
        int row = (ty << 2) + i;
        #pragma unroll
        for (int j = 0; j < 4; j++)
            C[row * ATTD + n0 + (tx << 2) + j] = acc[i][j];
    }
}

__global__ void k_tb_reduce(const float* __restrict__ b1) {
    int i = blockIdx.x * blockDim.x + threadIdx.x;
    if (i >= BATCH * ATTD) return;
    float s = b1[i & (ATTD - 1)];
    #pragma unroll
    for (int z = 0; z < 8; z++) s += g_tbp[z][i];
    g_tb[i] = s;
}

// ------------------------- K4: persistent GRU v3 -----------------------------
// 128 blocks = 2 dir x 64 j-tiles(8). 256 thr: j = tid&7, bg = tid>>3 (0..31),
// batches (2bg, 2bg+1). Whh slice (48KB) staged in smem ONCE; h-state read via
// ld.cg quads; inner loop per 4k: 3 LDS.128 + 2 LDG.128 + 12 FFMA2, no dups.
__global__ __launch_bounds__(256) void k_gru_persistent(
    const float* __restrict__ Wf, const float* __restrict__ Wb,
    const float* __restrict__ bf, const float* __restrict__ bb)
{
    __shared__ __align__(16) float Ws[128*24*4];   // [k4][gate*8+j][4k] = 48KB

    int blk = blockIdx.x;
    int dir = blk >> 6;
    int j0  = (blk & 63) << 3;
    int tid = threadIdx.x;
    int j   = tid & 7;
    int bg  = tid >> 3;
    int b0  = bg << 1;

    const float* W  = dir ? Wb : Wf;
    const float* bh = dir ? bb : bf;

    // one-time W staging: 6144 float4
    for (int i = tid; i < 128*24; i += 256) {
        int k4 = i / 24;
        int r  = i - k4*24;               // gate*8 + jj
        int g  = r >> 3, jj = r & 7;
        float4 v = *(const float4*)&W[(long)((g << 9) + j0 + jj) * HID + (k4 << 2)];
        *(float4*)&Ws[i << 2] = v;
    }
    __syncthreads();

    int jg = j0 + j;
    float br = __ldg(&bh[jg]);
    float bz = __ldg(&bh[HID + jg]);
    float bn = __ldg(&bh[2*HID + jg]);

    const float* xw = g_xw[dir];
    long xrow0 = ((long)b0 * SEQ) * (3*HID);
    long xrow1 = ((long)(b0+1) * SEQ) * (3*HID);
    int wbase = j << 2;
    int leak0 = ((jg >> 1) << 7) + (bg << 2) + (jg & 1);
    int leak1 = leak0 + 2;

    for (int t = 0; t < SEQ; t++) {
        const float* sp = g_state[t & 1][dir];
        float*       sn = g_state[(t+1) & 1][dir];
        int tt = dir ? (SEQ-1-t) : t;

        long xo0 = xrow0 + (long)tt * (3*HID);
        long xo1 = xrow1 + (long)tt * (3*HID);
        float xr0 = __ldg(&xw[xo0 + jg]);
        float xz0 = __ldg(&xw[xo0 + HID + jg]);
        float xn0 = __ldg(&xw[xo0 + 2*HID + jg]);
        float xr1 = __ldg(&xw[xo1 + jg]);
        float xz1 = __ldg(&xw[xo1 + HID + jg]);
        float xn1 = __ldg(&xw[xo1 + 2*HID + jg]);
        float hp0, hp1;
        asm("ld.global.cg.f32 %0, [%1];" : "=f"(hp0) : "l"(sp + leak0));
        asm("ld.global.cg.f32 %0, [%1];" : "=f"(hp1) : "l"(sp + leak1));

        u64 ar0 = 0, ar1 = 0, az0 = 0, az1 = 0, an0 = 0, an1 = 0;

        #pragma unroll 4
        for (int k4 = 0; k4 < 128; k4++) {
            const float* wp = Ws + k4 * 96;
            ulonglong2 wr = *(const ulonglong2*)(wp + wbase);
            ulonglong2 wz = *(const ulonglong2*)(wp + 32 + wbase);
            ulonglong2 wn = *(const ulonglong2*)(wp + 64 + wbase);
            u64 h0A, h0B, h1A, h1B;
            const float* hp = sp + (k4 << 8) + (bg << 2);
            ldg_cg_2x64(hp,       h0A, h0B);
            ldg_cg_2x64(hp + 128, h1A, h1B);
            ar0 = fma2(wr.x, h0A, ar0); ar1 = fma2(wr.x, h0B, ar1);
            az0 = fma2(wz.x, h0A, az0); az1 = fma2(wz.x, h0B, az1);
            an0 = fma2(wn.x, h0A, an0); an1 = fma2(wn.x, h0B, an1);
            ar0 = fma2(wr.y, h1A, ar0); ar1 = fma2(wr.y, h1B, ar1);
            az0 = fma2(wz.y, h1A, az0); az1 = fma2(wz.y, h1B, az1);
            an0 = fma2(wn.y, h1A, an0); an1 = fma2(wn.y, h1B, an1);
        }

        float2 u;
        u = unpack2(ar0); float gr0 = u.x + u.y + br;
        u = unpack2(ar1); float gr1 = u.x + u.y + br;
        u = unpack2(az0); float gz0 = u.x + u.y + bz;
        u = unpack2(az1); float gz1 = u.x + u.y + bz;
        u = unpack2(an0); float gn0 = u.x + u.y + bn;
        u = unpack2(an1); float gn1 = u.x + u.y + bn;

        float r0 = 1.f / (1.f + expf(-(xr0 + gr0)));
        float z0 = 1.f / (1.f + expf(-(xz0 + gz0)));
        float n0 = tanhf(xn0 + r0 * gn0);
        float h0 = (1.f - z0) * n0 + z0 * hp0;
        float r1 = 1.f / (1.f + expf(-(xr1 + gr1)));
        float z1 = 1.f / (1.f + expf(-(xz1 + gz1)));
        float n1 = tanhf(xn1 + r1 * gn1);
        float h1 = (1.f - z1) * n1 + z1 * hp1;

        sn[leak0] = h0;
        sn[leak1] = h1;
        g_h[((long)b0*SEQ + tt) * (2*HID) + dir*HID + jg] = h0;
        g_h[((long)(b0+1)*SEQ + tt) * (2*HID) + dir*HID + jg] = h1;

        if (t < SEQ - 1) {
            __syncthreads();
            if (tid == 0) {
                __threadfence();
                unsigned a = atomicAdd(&g_bar_cnt, 1u);
                if (a == GRU_BLOCKS - 1) {
                    g_bar_cnt = 0u;
                    __threadfence();
                    g_bar_gen = (unsigned)(t + 1);
                } else {
                    while (g_bar_gen < (unsigned)(t + 1)) { }
                }
            }
            __syncthreads();
        }
    }
}

// ------------------------- K5: masked mean pooling ---------------------------
__global__ void k_pool(const int* __restrict__ ts, const int* __restrict__ te) {
    int b = blockIdx.x;
    int s0 = ts[b], s1 = te[b];
    float inv = 1.f / (float)(s1 - s0 + 1);
    for (int c = threadIdx.x; c < 2*HID; c += blockDim.x) {
        float a = 0.f;
        for (int s = s0; s <= s1; s++)
            a += g_h[((long)b * SEQ + s) * (2*HID) + c];
        g_target[b * 2*HID + c] = a * inv;
    }
}

// ------------------------- K8: row softmax over S ----------------------------
__global__ void k_softmax() {
    int row = blockIdx.x * (blockDim.x >> 5) + (threadIdx.x >> 5);
    int lane = threadIdx.x & 31;
    float* p = g_alfa + (long)row * SEQ;
    float v[8];
    float mx = -1e30f;
    #pragma unroll
    for (int i = 0; i < 8; i++) { v[i] = p[lane + 32*i]; mx = fmaxf(mx, v[i]); }
    mx = warp_max(mx);
    float s = 0.f;
    #pragma unroll
    for (int i = 0; i < 8; i++) { v[i] = expf(v[i] - mx); s += v[i]; }
    s = warp_sum(s);
    float inv = 1.f / s;
    #pragma unroll
    for (int i = 0; i < 8; i++) p[lane + 32*i] = v[i] * inv;
}

// ------------------------- K10: result @ W2^T + b2 ---------------------------
__global__ void k_final(const float* __restrict__ W2, const float* __restrict__ b2,
                        float* __restrict__ out) {
    int row = blockIdx.x * 8 + (threadIdx.x >> 5);
    int lane = threadIdx.x & 31;
    const float* R = g_att + (long)row * (2*HID);
    float a0 = 0.f, a1 = 0.f, a2 = 0.f;
    for (int h = lane; h < 2*HID; h += 32) {
        float r = R[h];
        a0 = fmaf(r, W2[h],           a0);
        a1 = fmaf(r, W2[2*HID + h],   a1);
        a2 = fmaf(r, W2[4*HID + h],   a2);
    }
    a0 = warp_sum(a0); a1 = warp_sum(a1); a2 = warp_sum(a2);
    if (lane == 0) {
        out[row*3 + 0] = a0 + b2[0];
        out[row*3 + 1] = a1 + b2[1];
        out[row*3 + 2] = a2 + b2[2];
    }
}

// ------------------------- launcher ------------------------------------------
extern "C" void kernel_launch(void* const* d_in, const int* in_sizes, int n_in,
                              void* d_out, int out_size) {
    const int*   x      = (const int*)  d_in[0];
    const int*   tstart = (const int*)  d_in[1];
    const int*   tend   = (const int*)  d_in[2];
    const float* emb    = (const float*)d_in[3];
    const float* Wih_f  = (const float*)d_in[4];
    const float* Whh_f  = (const float*)d_in[5];
    const float* bih_f  = (const float*)d_in[6];
    const float* bhh_f  = (const float*)d_in[7];
    const float* Wih_b  = (const float*)d_in[8];
    const float* Whh_b  = (const float*)d_in[9];
    const float* bih_b  = (const float*)d_in[10];
    const float* bhh_b  = (const float*)d_in[11];
    const float* W1     = (const float*)d_in[12];
    const float* b1     = (const float*)d_in[13];
    const float* u      = (const float*)d_in[14];
    const float* W2     = (const float*)d_in[15];
    const float* b2     = (const float*)d_in[16];
    float* out = (float*)d_out;

    float *p_e, *p_xw, *p_h, *p_target, *p_tb, *p_o, *p_alfa, *p_att;
    cudaGetSymbolAddress((void**)&p_e,      g_e);
    cudaGetSymbolAddress((void**)&p_xw,     g_xw);
    cudaGetSymbolAddress((void**)&p_h,      g_h);
    cudaGetSymbolAddress((void**)&p_target, g_target);
    cudaGetSymbolAddress((void**)&p_tb,     g_tb);
    cudaGetSymbolAddress((void**)&p_o,      g_o);
    cudaGetSymbolAddress((void**)&p_alfa,   g_alfa);
    cudaGetSymbolAddress((void**)&p_att,    g_att);
    float* p_xw0 = p_xw;
    float* p_xw1 = p_xw + (long)NROWS * 3 * HID;

    k_zero_state<<<512, 256>>>();
    k_embed<<<2048, 256>>>(x, emb);

    // input projections: [16384,300] x [1536,300]^T (+bih)
    k_gemm_nt<<<dim3(128, 12, 1), 256>>>(p_e, Wih_f, p_xw0, EDIM,
                                         EDIM, EDIM, 3*HID, 0, 0, 0,
                                         bih_f, nullptr, 0);
    k_gemm_nt<<<dim3(128, 12, 1), 256>>>(p_e, Wih_b, p_xw1, EDIM,
                                         EDIM, EDIM, 3*HID, 0, 0, 0,
                                         bih_b, nullptr, 0);

    // full recurrence in ONE persistent kernel
    k_gru_persistent<<<GRU_BLOCKS, 256>>>(Whh_f, Whh_b, bhh_f, bhh_b);

    // masked mean pool over target span
    k_pool<<<64, 256>>>(tstart, tend);

    // tb = target . W1[:,1024:]^T + b1  (split-K 8 + reduce)
    k_gemm_target<<<dim3(1, 4, 8), 256>>>(p_target, W1 + 1024);
    k_tb_reduce<<<64, 256>>>(b1);

    // o = tanh(h . W1[:,:1024]^T + tb[b])   (M=16384,N=256,K=1024)
    k_gemm_nt<<<dim3(128, 2, 1), 256>>>(p_h, W1, p_o, 2*HID,
                                        2*HID, 4*HID, ATTD, 0, 0, 0,
                                        nullptr, p_tb, 1);

    // beta[b,k,s] = u[k] . o[b,s]           (batched NT, 256x256x256)
    k_gemm_nt<<<dim3(2, 2, 64), 256>>>(u, p_o, p_alfa, ATTD,
                                       ATTD, ATTD, SEQ,
                                       0, (long)SEQ*ATTD, (long)ATTD*SEQ,
                                       nullptr, nullptr, 2);

    // softmax over s
    k_softmax<<<2048, 256>>>();

    // result[b,k,:] = alfa[b,k,:] . h[b]    (batched NN, 256x1024x256)
    k_gemm_nn<<<dim3(2, 8, 64), 256>>>(p_alfa, p_h, p_att, SEQ,
                                       SEQ, 2*HID, 2*HID,
                                       (long)ATTD*SEQ, (long)SEQ*2*HID,
                                       (long)ATTD*2*HID);

    // final projection to 3 labels
    k_final<<<2048, 256>>>(W2, b2, out);
}

// round 8
// speedup vs baseline: 1.7665x; 1.2349x over previous
#include <cuda_runtime.h>
#include <math.h>

#define BATCH 64
#define SEQ   256
#define EDIM  300
#define HID   512
#define ATTD  256
#define NROWS (BATCH*SEQ)          // 16384
#define GRU_BLOCKS 128

typedef unsigned long long u64;

// ------------------------- scratch (static device memory) -------------------
__device__ float g_e[NROWS*EDIM];              // renormed embeddings  [16384,300]
__device__ float g_xw[2][NROWS*3*HID];         // input projections    [dir][b*256+s][1536]
__device__ float g_h[NROWS*2*HID];             // concat hidden        [b,s,1024]
// state quads: [parity][dir][k2*128 + bg*4 + bp*2 + kp]  (k=2*k2+kp, b=2*bg+bp)
__device__ float g_state[2][2][HID*BATCH];
__device__ float g_target[BATCH*2*HID];        // pooled target        [64,1024]
__device__ float g_tbp[8][BATCH*ATTD];         // split-K partials
__device__ float g_tb[BATCH*ATTD];             // target@W1b + b1      [64,256]
__device__ float g_o[NROWS*ATTD];              // tanh attention feats [16384,256]
__device__ float g_alfa[BATCH*ATTD*SEQ];       // beta -> alfa         [64,256,256]
__device__ float g_att[NROWS*2*HID];           // result               [b*256+k,1024]

__device__ volatile unsigned g_bar_gen;
__device__ unsigned g_bar_cnt;

// ------------------------- helpers -------------------------------------------
__device__ __forceinline__ u64 dup2(float w) {
    u64 r; asm("mov.b64 %0, {%1, %1};" : "=l"(r) : "f"(w)); return r;
}
__device__ __forceinline__ u64 fma2(u64 a, u64 b, u64 c) {
    u64 d; asm("fma.rn.f32x2 %0, %1, %2, %3;" : "=l"(d) : "l"(a), "l"(b), "l"(c));
    return d;
}
__device__ __forceinline__ float2 unpack2(u64 v) {
    float2 f; asm("mov.b64 {%0, %1}, %2;" : "=f"(f.x), "=f"(f.y) : "l"(v)); return f;
}
__device__ __forceinline__ unsigned smem_u32(const void* p) {
    unsigned a;
    asm("{ .reg .u64 t; cvta.to.shared.u64 t, %1; cvt.u32.u64 %0, t; }"
        : "=r"(a) : "l"(p));
    return a;
}
__device__ __forceinline__ void cpasync16(unsigned s, const void* g) {
    asm volatile("cp.async.cg.shared.global [%0], [%1], 16;" :: "r"(s), "l"(g));
}
__device__ __forceinline__ float warp_sum(float v) {
    #pragma unroll
    for (int o = 16; o > 0; o >>= 1) v += __shfl_xor_sync(0xffffffffu, v, o);
    return v;
}
__device__ __forceinline__ float warp_max(float v) {
    #pragma unroll
    for (int o = 16; o > 0; o >>= 1) v = fmaxf(v, __shfl_xor_sync(0xffffffffu, v, o));
    return v;
}

// ------------------------- K0: zero GRU state + barrier ----------------------
__global__ void k_zero_state() {
    int i = blockIdx.x * blockDim.x + threadIdx.x;
    if (i < 2*2*HID*BATCH) ((float*)g_state)[i] = 0.f;
    if (i == 0) { g_bar_gen = 0u; g_bar_cnt = 0u; }
}

// ------------------------- K1: embedding gather + renorm ---------------------
__global__ void k_embed(const int* __restrict__ x, const float* __restrict__ emb) {
    int w = blockIdx.x * (blockDim.x >> 5) + (threadIdx.x >> 5);
    int lane = threadIdx.x & 31;
    if (w >= NROWS) return;
    const float* src = emb + (long)x[w] * EDIM;
    float v[10];
    float ss = 0.f;
    #pragma unroll
    for (int i = 0; i < 10; i++) {
        int c = lane + 32*i;
        float t = (c < EDIM) ? __ldg(src + c) : 0.f;
        v[i] = t; ss += t*t;
    }
    ss = warp_sum(ss);
    float sc = fminf(1.f, 5.f / (sqrtf(ss) + 1e-7f));
    float* dst = g_e + (long)w * EDIM;
    #pragma unroll
    for (int i = 0; i < 10; i++) {
        int c = lane + 32*i;
        if (c < EDIM) dst[c] = v[i] * sc;
    }
}

// ------------------------- K2: 128x128 FFMA2 GEMMs ---------------------------
#define GP 132
// NT: C[M,N] = A[M,K] . B[N,K]^T ; epi 0:+bias, 1:tanh(acc+tb2[(row>>8)*256+col]), 2:none
__global__ __launch_bounds__(256) void k_gemm_nt(
    const float* __restrict__ A, const float* __restrict__ B, float* __restrict__ C,
    int K, int lda, int ldb, int ldc, long sA, long sB, long sC,
    const float* __restrict__ bias, const float* __restrict__ tb2, int epi)
{
    __shared__ __align__(16) float As[16*GP];
    __shared__ __align__(16) float Bs[16*GP];
    int bz = blockIdx.z;
    A += sA * bz; B += sB * bz; C += sC * bz;
    int m0 = blockIdx.x << 7, n0 = blockIdx.y << 7;
    int tid = threadIdx.x;
    int tx = tid & 15, ty = tid >> 4;
    int srow = tid >> 1, skh = (tid & 1) << 3;
    const float* Ap = A + (long)(m0 + srow) * lda;
    const float* Bp = B + (long)(n0 + srow) * ldb;
    u64 acc[8][4] = {};
    for (int k0 = 0; k0 < K; k0 += 16) {
        if (k0 + 16 <= K) {
            float4 a0 = *(const float4*)(Ap + k0 + skh);
            float4 a1 = *(const float4*)(Ap + k0 + skh + 4);
            float4 b0 = *(const float4*)(Bp + k0 + skh);
            float4 b1 = *(const float4*)(Bp + k0 + skh + 4);
            As[(skh+0)*GP + srow] = a0.x; As[(skh+1)*GP + srow] = a0.y;
            As[(skh+2)*GP + srow] = a0.z; As[(skh+3)*GP + srow] = a0.w;
            As[(skh+4)*GP + srow] = a1.x; As[(skh+5)*GP + srow] = a1.y;
            As[(skh+6)*GP + srow] = a1.z; As[(skh+7)*GP + srow] = a1.w;
            Bs[(skh+0)*GP + srow] = b0.x; Bs[(skh+1)*GP + srow] = b0.y;
            Bs[(skh+2)*GP + srow] = b0.z; Bs[(skh+3)*GP + srow] = b0.w;
            Bs[(skh+4)*GP + srow] = b1.x; Bs[(skh+5)*GP + srow] = b1.y;
            Bs[(skh+6)*GP + srow] = b1.z; Bs[(skh+7)*GP + srow] = b1.w;
        } else {
            #pragma unroll
            for (int c = 0; c < 8; c++) {
                int kk = k0 + skh + c;
                As[(skh+c)*GP + srow] = (kk < K) ? Ap[kk] : 0.f;
                Bs[(skh+c)*GP + srow] = (kk < K) ? Bp[kk] : 0.f;
            }
        }
        __syncthreads();
        #pragma unroll
        for (int k = 0; k < 16; k++) {
            float a[8]; u64 bq[4];
            *(float4*)&a[0] = *(const float4*)&As[k*GP + (ty<<3)];
            *(float4*)&a[4] = *(const float4*)&As[k*GP + (ty<<3) + 4];
            ulonglong2 t0 = *(const ulonglong2*)&Bs[k*GP + (tx<<3)];
            ulonglong2 t1 = *(const ulonglong2*)&Bs[k*GP + (tx<<3) + 4];
            bq[0] = t0.x; bq[1] = t0.y; bq[2] = t1.x; bq[3] = t1.y;
            #pragma unroll
            for (int i = 0; i < 8; i++) {
                u64 ad = dup2(a[i]);
                acc[i][0] = fma2(ad, bq[0], acc[i][0]);
                acc[i][1] = fma2(ad, bq[1], acc[i][1]);
                acc[i][2] = fma2(ad, bq[2], acc[i][2]);
                acc[i][3] = fma2(ad, bq[3], acc[i][3]);
            }
        }
        __syncthreads();
    }
    #pragma unroll
    for (int i = 0; i < 8; i++) {
        int row = m0 + (ty << 3) + i;
        float v[8];
        #pragma unroll
        for (int p = 0; p < 4; p++) {
            float2 u = unpack2(acc[i][p]);
            v[2*p] = u.x; v[2*p+1] = u.y;
        }
        #pragma unroll
        for (int j = 0; j < 8; j++) {
            int col = n0 + (tx << 3) + j;
            if (epi == 0)      v[j] += bias[col];
            else if (epi == 1) v[j] = tanhf(v[j] + tb2[((row >> 8) << 8) + col]);
        }
        float* cp = C + (long)row * ldc + n0 + (tx << 3);
        *(float4*)cp       = make_float4(v[0], v[1], v[2], v[3]);
        *(float4*)(cp + 4) = make_float4(v[4], v[5], v[6], v[7]);
    }
}

// NN: C[M,N] = A[M,K] . B[K,N]  (K multiple of 16)
__global__ __launch_bounds__(256) void k_gemm_nn(
    const float* __restrict__ A, const float* __restrict__ B, float* __restrict__ C,
    int K, int lda, int ldb, int ldc, long sA, long sB, long sC)
{
    __shared__ __align__(16) float As[16*GP];
    __shared__ __align__(16) float Bs[16*GP];
    int bz = blockIdx.z;
    A += sA * bz; B += sB * bz; C += sC * bz;
    int m0 = blockIdx.x << 7, n0 = blockIdx.y << 7;
    int tid = threadIdx.x;
    int tx = tid & 15, ty = tid >> 4;
    int srow = tid >> 1, skh = (tid & 1) << 3;
    int bkk = tid >> 4, bc8 = (tid & 15) << 3;
    const float* Ap = A + (long)(m0 + srow) * lda;
    u64 acc[8][4] = {};
    for (int k0 = 0; k0 < K; k0 += 16) {
        {
            float4 a0 = *(const float4*)(Ap + k0 + skh);
            float4 a1 = *(const float4*)(Ap + k0 + skh + 4);
            As[(skh+0)*GP + srow] = a0.x; As[(skh+1)*GP + srow] = a0.y;
            As[(skh+2)*GP + srow] = a0.z; As[(skh+3)*GP + srow] = a0.w;
            As[(skh+4)*GP + srow] = a1.x; As[(skh+5)*GP + srow] = a1.y;
            As[(skh+6)*GP + srow] = a1.z; As[(skh+7)*GP + srow] = a1.w;
            const float* bp = B + (long)(k0 + bkk) * ldb + n0 + bc8;
            float4 b0 = *(const float4*)bp;
            float4 b1 = *(const float4*)(bp + 4);
            *(float4*)&Bs[bkk*GP + bc8]     = b0;
            *(float4*)&Bs[bkk*GP + bc8 + 4] = b1;
        }
        __syncthreads();
        #pragma unroll
        for (int k = 0; k < 16; k++) {
            float a[8]; u64 bq[4];
            *(float4*)&a[0] = *(const float4*)&As[k*GP + (ty<<3)];
            *(float4*)&a[4] = *(const float4*)&As[k*GP + (ty<<3) + 4];
            ulonglong2 t0 = *(const ulonglong2*)&Bs[k*GP + (tx<<3)];
            ulonglong2 t1 = *(const ulonglong2*)&Bs[k*GP + (tx<<3) + 4];
            bq[0] = t0.x; bq[1] = t0.y; bq[2] = t1.x; bq[3] = t1.y;
            #pragma unroll
            for (int i = 0; i < 8; i++) {
                u64 ad = dup2(a[i]);
                acc[i][0] = fma2(ad, bq[0], acc[i][0]);
                acc[i][1] = fma2(ad, bq[1], acc[i][1]);
                acc[i][2] = fma2(ad, bq[2], acc[i][2]);
                acc[i][3] = fma2(ad, bq[3], acc[i][3]);
            }
        }
        __syncthreads();
    }
    #pragma unroll
    for (int i = 0; i < 8; i++) {
        int row = m0 + (ty << 3) + i;
        float v[8];
        #pragma unroll
        for (int p = 0; p < 4; p++) {
            float2 u = unpack2(acc[i][p]);
            v[2*p] = u.x; v[2*p+1] = u.y;
        }
        float* cp = C + (long)row * ldc + n0 + (tx << 3);
        *(float4*)cp       = make_float4(v[0], v[1], v[2], v[3]);
        *(float4*)(cp + 4) = make_float4(v[4], v[5], v[6], v[7]);
    }
}

// ------------------------- K3: small split-K NT for target -------------------
__global__ __launch_bounds__(256) void k_gemm_target(
    const float* __restrict__ A, const float* __restrict__ B)
{
    __shared__ __align__(16) float As[16][64];
    __shared__ __align__(16) float Bs[16][64];
    int z = blockIdx.z;
    A += z * 128;      // lda 1024
    B += z * 128;      // ldb 2048
    float* C = g_tbp[z];
    int n0 = blockIdx.y << 6;
    int tid = threadIdx.x;
    int tx = tid & 15, ty = tid >> 4;
    float acc[4][4] = {};
    for (int k0 = 0; k0 < 128; k0 += 16) {
        int r = tid >> 2;
        int cb = (tid & 3) << 2;
        #pragma unroll
        for (int p = 0; p < 4; p++) {
            int c = cb + p;
            As[c][r] = A[(long)r * (2*HID) + k0 + c];
            Bs[c][r] = B[(long)(n0 + r) * (4*HID) + k0 + c];
        }
        __syncthreads();
        #pragma unroll
        for (int k = 0; k < 16; k++) {
            float4 av = *(const float4*)&As[k][ty << 2];
            float4 bv = *(const float4*)&Bs[k][tx << 2];
            float a[4] = {av.x, av.y, av.z, av.w};
            float b[4] = {bv.x, bv.y, bv.z, bv.w};
            #pragma unroll
            for (int i = 0; i < 4; i++)
                #pragma unroll
                for (int j = 0; j < 4; j++)
                    acc[i][j] = fmaf(a[i], b[j], acc[i][j]);
        }
        __syncthreads();
    }
    #pragma unroll
    for (int i = 0; i < 4; i++) {
        int row = (ty << 2) + i;
        #pragma unroll
        for (int j = 0; j < 4; j++)
            C[row * ATTD + n0 + (tx << 2) + j] = acc[i][j];
    }
}

__global__ void k_tb_reduce(const float* __restrict__ b1) {
    int i = blockIdx.x * blockDim.x + threadIdx.x;
    if (i >= BATCH * ATTD) return;
    float s = b1[i & (ATTD - 1)];
    #pragma unroll
    for (int z = 0; z < 8; z++) s += g_tbp[z][i];
    g_tb[i] = s;
}

// ------------------------- K4: persistent GRU v4 (cp.async staged) -----------
// 128 blocks = 2 dir x 64 j-tiles(8). 256 thr: j = tid&7, bg = tid>>3 (0..31),
// batches (2bg, 2bg+1). W slice (48KB) in smem for the whole kernel; state
// (128KB) staged into smem per step via cp.async.cg, 4 chunks pipelined against
// the FFMA2 compute. Inner loop: 5 dedup'd LDS.128 + 12 FFMA2 per 4k.
// Leak term carried in registers (thread re-reads its own h).
#define GRU_SMEM (48*1024 + 128*1024)
__global__ __launch_bounds__(256, 1) void k_gru_persistent(
    const float* __restrict__ Wf, const float* __restrict__ Wb,
    const float* __restrict__ bf, const float* __restrict__ bb)
{
    extern __shared__ __align__(16) float smem[];
    float* Ws = smem;              // 12288 floats [k4][gate*8+j][4]
    float* Hs = smem + 12288;      // 32768 floats, same quad layout as g_state

    int blk = blockIdx.x;
    int dir = blk >> 6;
    int j0  = (blk & 63) << 3;
    int tid = threadIdx.x;
    int j   = tid & 7;
    int bg  = tid >> 3;
    int b0  = bg << 1;

    const float* W  = dir ? Wb : Wf;
    const float* bh = dir ? bb : bf;

    // one-time W staging: 6144 float4
    for (int i = tid; i < 128*24; i += 256) {
        int k4 = i / 24;
        int r  = i - k4*24;               // gate*8 + jj
        int g  = r >> 3, jj = r & 7;
        float4 v = *(const float4*)&W[(long)((g << 9) + j0 + jj) * HID + (k4 << 2)];
        *(float4*)&Ws[i << 2] = v;
    }
    __syncthreads();

    int jg = j0 + j;
    float br = __ldg(&bh[jg]);
    float bz = __ldg(&bh[HID + jg]);
    float bn = __ldg(&bh[2*HID + jg]);

    const float* xw = g_xw[dir];
    long xrow0 = ((long)b0 * SEQ) * (3*HID);
    long xrow1 = ((long)(b0+1) * SEQ) * (3*HID);
    int wbase = j << 2;
    int leak0 = ((jg >> 1) << 7) + (bg << 2) + (jg & 1);
    int leak1 = leak0 + 2;
    unsigned hs_base = smem_u32(Hs);

    float hp0 = 0.f, hp1 = 0.f;          // leak state carried in registers

    for (int t = 0; t < SEQ; t++) {
        const float* sp = g_state[t & 1][dir];
        float*       sn = g_state[(t+1) & 1][dir];
        int tt = dir ? (SEQ-1-t) : t;

        long xo0 = xrow0 + (long)tt * (3*HID);
        long xo1 = xrow1 + (long)tt * (3*HID);
        float xr0 = __ldg(&xw[xo0 + jg]);
        float xz0 = __ldg(&xw[xo0 + HID + jg]);
        float xn0 = __ldg(&xw[xo0 + 2*HID + jg]);
        float xr1 = __ldg(&xw[xo1 + jg]);
        float xz1 = __ldg(&xw[xo1 + HID + jg]);
        float xn1 = __ldg(&xw[xo1 + 2*HID + jg]);

        const float4* sp4 = (const float4*)sp;

        // stage chunk 0 (32 k4 = 32KB = 2048 float4; 8 cp.async per thread)
        {
            int base = tid;
            #pragma unroll
            for (int p = 0; p < 8; p++)
                cpasync16(hs_base + ((unsigned)(base + (p << 8)) << 4),
                          sp4 + base + (p << 8));
            asm volatile("cp.async.commit_group;" ::: "memory");
        }

        u64 ar0 = 0, ar1 = 0, az0 = 0, az1 = 0, an0 = 0, an1 = 0;

        #pragma unroll 1
        for (int c = 0; c < 4; c++) {
            if (c < 3) {
                int base = (c + 1) * 2048 + tid;
                #pragma unroll
                for (int p = 0; p < 8; p++)
                    cpasync16(hs_base + ((unsigned)(base + (p << 8)) << 4),
                              sp4 + base + (p << 8));
                asm volatile("cp.async.commit_group;" ::: "memory");
                asm volatile("cp.async.wait_group 1;" ::: "memory");
            } else {
                asm volatile("cp.async.wait_group 0;" ::: "memory");
            }
            __syncthreads();

            int k4base = c << 5;
            #pragma unroll 8
            for (int kk = 0; kk < 32; kk++) {
                int k4 = k4base + kk;
                const float* wp = Ws + k4 * 96;
                ulonglong2 wr = *(const ulonglong2*)(wp + wbase);
                ulonglong2 wz = *(const ulonglong2*)(wp + 32 + wbase);
                ulonglong2 wn = *(const ulonglong2*)(wp + 64 + wbase);
                const float* hpp = Hs + (k4 << 8) + (bg << 2);
                ulonglong2 hA = *(const ulonglong2*)hpp;
                ulonglong2 hB = *(const ulonglong2*)(hpp + 128);
                ar0 = fma2(wr.x, hA.x, ar0); ar1 = fma2(wr.x, hA.y, ar1);
                az0 = fma2(wz.x, hA.x, az0); az1 = fma2(wz.x, hA.y, az1);
                an0 = fma2(wn.x, hA.x, an0); an1 = fma2(wn.x, hA.y, an1);
                ar0 = fma2(wr.y, hB.x, ar0); ar1 = fma2(wr.y, hB.y, ar1);
                az0 = fma2(wz.y, hB.x, az0); az1 = fma2(wz.y, hB.y, az1);
                an0 = fma2(wn.y, hB.x, an0); an1 = fma2(wn.y, hB.y, an1);
            }
        }

        float2 u;
        u = unpack2(ar0); float gr0 = u.x + u.y + br;
        u = unpack2(ar1); float gr1 = u.x + u.y + br;
        u = unpack2(az0); float gz0 = u.x + u.y + bz;
        u = unpack2(az1); float gz1 = u.x + u.y + bz;
        u = unpack2(an0); float gn0 = u.x + u.y + bn;
        u = unpack2(an1); float gn1 = u.x + u.y + bn;

        float r0 = 1.f / (1.f + expf(-(xr0 + gr0)));
        float z0 = 1.f / (1.f + expf(-(xz0 + gz0)));
        float n0 = tanhf(xn0 + r0 * gn0);
        float h0 = (1.f - z0) * n0 + z0 * hp0;
        float r1 = 1.f / (1.f + expf(-(xr1 + gr1)));
        float z1 = 1.f / (1.f + expf(-(xz1 + gz1)));
        float n1 = tanhf(xn1 + r1 * gn1);
        float h1 = (1.f - z1) * n1 + z1 * hp1;
        hp0 = h0; hp1 = h1;

        sn[leak0] = h0;
        sn[leak1] = h1;
        g_h[((long)b0*SEQ + tt) * (2*HID) + dir*HID + jg] = h0;
        g_h[((long)(b0+1)*SEQ + tt) * (2*HID) + dir*HID + jg] = h1;

        if (t < SEQ - 1) {
            __syncthreads();
            if (tid == 0) {
                __threadfence();
                unsigned a = atomicAdd(&g_bar_cnt, 1u);
                if (a == GRU_BLOCKS - 1) {
                    g_bar_cnt = 0u;
                    __threadfence();
                    g_bar_gen = (unsigned)(t + 1);
                } else {
                    while (g_bar_gen < (unsigned)(t + 1)) { }
                }
            }
            __syncthreads();
        }
    }
}

// ------------------------- K5: masked mean pooling ---------------------------
__global__ void k_pool(const int* __restrict__ ts, const int* __restrict__ te) {
    int b = blockIdx.x;
    int s0 = ts[b], s1 = te[b];
    float inv = 1.f / (float)(s1 - s0 + 1);
    for (int c = threadIdx.x; c < 2*HID; c += blockDim.x) {
        float a = 0.f;
        for (int s = s0; s <= s1; s++)
            a += g_h[((long)b * SEQ + s) * (2*HID) + c];
        g_target[b * 2*HID + c] = a * inv;
    }
}

// ------------------------- K8: row softmax over S ----------------------------
__global__ void k_softmax() {
    int row = blockIdx.x * (blockDim.x >> 5) + (threadIdx.x >> 5);
    int lane = threadIdx.x & 31;
    float* p = g_alfa + (long)row * SEQ;
    float v[8];
    float mx = -1e30f;
    #pragma unroll
    for (int i = 0; i < 8; i++) { v[i] = p[lane + 32*i]; mx = fmaxf(mx, v[i]); }
    mx = warp_max(mx);
    float s = 0.f;
    #pragma unroll
    for (int i = 0; i < 8; i++) { v[i] = expf(v[i] - mx); s += v[i]; }
    s = warp_sum(s);
    float inv = 1.f / s;
    #pragma unroll
    for (int i = 0; i < 8; i++) p[lane + 32*i] = v[i] * inv;
}

// ------------------------- K10: result @ W2^T + b2 ---------------------------
__global__ void k_final(const float* __restrict__ W2, const float* __restrict__ b2,
                        float* __restrict__ out) {
    int row = blockIdx.x * 8 + (threadIdx.x >> 5);
    int lane = threadIdx.x & 31;
    const float* R = g_att + (long)row * (2*HID);
    float a0 = 0.f, a1 = 0.f, a2 = 0.f;
    for (int h = lane; h < 2*HID; h += 32) {
        float r = R[h];
        a0 = fmaf(r, W2[h],           a0);
        a1 = fmaf(r, W2[2*HID + h],   a1);
        a2 = fmaf(r, W2[4*HID + h],   a2);
    }
    a0 = warp_sum(a0); a1 = warp_sum(a1); a2 = warp_sum(a2);
    if (lane == 0) {
        out[row*3 + 0] = a0 + b2[0];
        out[row*3 + 1] = a1 + b2[1];
        out[row*3 + 2] = a2 + b2[2];
    }
}

// ------------------------- launcher ------------------------------------------
extern "C" void kernel_launch(void* const* d_in, const int* in_sizes, int n_in,
                              void* d_out, int out_size) {
    const int*   x      = (const int*)  d_in[0];
    const int*   tstart = (const int*)  d_in[1];
    const int*   tend   = (const int*)  d_in[2];
    const float* emb    = (const float*)d_in[3];
    const float* Wih_f  = (const float*)d_in[4];
    const float* Whh_f  = (const float*)d_in[5];
    const float* bih_f  = (const float*)d_in[6];
    const float* bhh_f  = (const float*)d_in[7];
    const float* Wih_b  = (const float*)d_in[8];
    const float* Whh_b  = (const float*)d_in[9];
    const float* bih_b  = (const float*)d_in[10];
    const float* bhh_b  = (const float*)d_in[11];
    const float* W1     = (const float*)d_in[12];
    const float* b1     = (const float*)d_in[13];
    const float* u      = (const float*)d_in[14];
    const float* W2     = (const float*)d_in[15];
    const float* b2     = (const float*)d_in[16];
    float* out = (float*)d_out;

    static int smem_set = 0;
    if (!smem_set) {
        cudaFuncSetAttribute(k_gru_persistent,
                             cudaFuncAttributeMaxDynamicSharedMemorySize, GRU_SMEM);
        smem_set = 1;
    }

    float *p_e, *p_xw, *p_h, *p_target, *p_tb, *p_o, *p_alfa, *p_att;
    cudaGetSymbolAddress((void**)&p_e,      g_e);
    cudaGetSymbolAddress((void**)&p_xw,     g_xw);
    cudaGetSymbolAddress((void**)&p_h,      g_h);
    cudaGetSymbolAddress((void**)&p_target, g_target);
    cudaGetSymbolAddress((void**)&p_tb,     g_tb);
    cudaGetSymbolAddress((void**)&p_o,      g_o);
    cudaGetSymbolAddress((void**)&p_alfa,   g_alfa);
    cudaGetSymbolAddress((void**)&p_att,    g_att);
    float* p_xw0 = p_xw;
    float* p_xw1 = p_xw + (long)NROWS * 3 * HID;

    k_zero_state<<<512, 256>>>();
    k_embed<<<2048, 256>>>(x, emb);

    // input projections: [16384,300] x [1536,300]^T (+bih)
    k_gemm_nt<<<dim3(128, 12, 1), 256>>>(p_e, Wih_f, p_xw0, EDIM,
                                         EDIM, EDIM, 3*HID, 0, 0, 0,
                                         bih_f, nullptr, 0);
    k_gemm_nt<<<dim3(128, 12, 1), 256>>>(p_e, Wih_b, p_xw1, EDIM,
                                         EDIM, EDIM, 3*HID, 0, 0, 0,
                                         bih_b, nullptr, 0);

    // full recurrence in ONE persistent kernel
    k_gru_persistent<<<GRU_BLOCKS, 256, GRU_SMEM>>>(Whh_f, Whh_b, bhh_f, bhh_b);

    // masked mean pool over target span
    k_pool<<<64, 256>>>(tstart, tend);

    // tb = target . W1[:,1024:]^T + b1  (split-K 8 + reduce)
    k_gemm_target<<<dim3(1, 4, 8), 256>>>(p_target, W1 + 1024);
    k_tb_reduce<<<64, 256>>>(b1);

    // o = tanh(h . W1[:,:1024]^T + tb[b])   (M=16384,N=256,K=1024)
    k_gemm_nt<<<dim3(128, 2, 1), 256>>>(p_h, W1, p_o, 2*HID,
                                        2*HID, 4*HID, ATTD, 0, 0, 0,
                                        nullptr, p_tb, 1);

    // beta[b,k,s] = u[k] . o[b,s]           (batched NT, 256x256x256)
    k_gemm_nt<<<dim3(2, 2, 64), 256>>>(u, p_o, p_alfa, ATTD,
                                       ATTD, ATTD, SEQ,
                                       0, (long)SEQ*ATTD, (long)ATTD*SEQ,
                                       nullptr, nullptr, 2);

    // softmax over s
    k_softmax<<<2048, 256>>>();

    // result[b,k,:] = alfa[b,k,:] . h[b]    (batched NN, 256x1024x256)
    k_gemm_nn<<<dim3(2, 8, 64), 256>>>(p_alfa, p_h, p_att, SEQ,
                                       SEQ, 2*HID, 2*HID,
                                       (long)ATTD*SEQ, (long)SEQ*2*HID,
                                       (long)ATTD*2*HID);

    // final projection to 3 labels
    k_final<<<2048, 256>>>(W2, b2, out);
}

// round 10
// speedup vs baseline: 1.9029x; 1.0772x over previous
#include <cuda_runtime.h>
#include <math.h>

#define BATCH 64
#define SEQ   256
#define EDIM  300
#define HID   512
#define ATTD  256
#define NROWS (BATCH*SEQ)          // 16384
#define GRU_BLOCKS 128

typedef unsigned long long u64;

// ------------------------- scratch (static device memory) -------------------
__device__ float g_e[NROWS*EDIM];              // renormed embeddings  [16384,300]
__device__ float g_xw[2][NROWS*3*HID];         // input projections    [dir][b*256+s][1536]
__device__ float g_h[NROWS*2*HID];             // concat hidden        [b,s,1024]
__device__ float g_state[2][2][HID*BATCH];     // [parity][dir][k][64b]  plain layout
__device__ float g_target[BATCH*2*HID];        // pooled target        [64,1024]
__device__ float g_tbp[8][BATCH*ATTD];         // split-K partials
__device__ float g_tb[BATCH*ATTD];             // target@W1b + b1      [64,256]
__device__ float g_o[NROWS*ATTD];              // tanh attention feats [16384,256]
__device__ float g_alfa[BATCH*ATTD*SEQ];       // beta -> alfa         [64,256,256]
__device__ float g_att[NROWS*2*HID];           // result               [b*256+k,1024]

__device__ volatile unsigned g_bar_gen;
__device__ unsigned g_bar_cnt;

// ------------------------- helpers -------------------------------------------
__device__ __forceinline__ u64 dup2(float w) {
    u64 r; asm("mov.b64 %0, {%1, %1};" : "=l"(r) : "f"(w)); return r;
}
__device__ __forceinline__ u64 fma2(u64 a, u64 b, u64 c) {
    u64 d; asm("fma.rn.f32x2 %0, %1, %2, %3;" : "=l"(d) : "l"(a), "l"(b), "l"(c));
    return d;
}
__device__ __forceinline__ u64 add2(u64 a, u64 b) {
    u64 d; asm("add.rn.f32x2 %0, %1, %2;" : "=l"(d) : "l"(a), "l"(b));
    return d;
}
__device__ __forceinline__ float2 unpack2(u64 v) {
    float2 f; asm("mov.b64 {%0, %1}, %2;" : "=f"(f.x), "=f"(f.y) : "l"(v)); return f;
}
__device__ __forceinline__ unsigned smem_u32(const void* p) {
    unsigned a;
    asm("{ .reg .u64 t; cvta.to.shared.u64 t, %1; cvt.u32.u64 %0, t; }"
        : "=r"(a) : "l"(p));
    return a;
}
__device__ __forceinline__ void cpasync16(unsigned s, const void* g) {
    asm volatile("cp.async.cg.shared.global [%0], [%1], 16;" :: "r"(s), "l"(g));
}
__device__ __forceinline__ float warp_sum(float v) {
    #pragma unroll
    for (int o = 16; o > 0; o >>= 1) v += __shfl_xor_sync(0xffffffffu, v, o);
    return v;
}
__device__ __forceinline__ float warp_max(float v) {
    #pragma unroll
    for (int o = 16; o > 0; o >>= 1) v = fmaxf(v, __shfl_xor_sync(0xffffffffu, v, o));
    return v;
}

// ------------------------- K0: zero GRU state + barrier ----------------------
__global__ void k_zero_state() {
    int i = blockIdx.x * blockDim.x + threadIdx.x;
    if (i < 2*2*HID*BATCH) ((float*)g_state)[i] = 0.f;
    if (i == 0) { g_bar_gen = 0u; g_bar_cnt = 0u; }
}

// ------------------------- K1: embedding gather + renorm ---------------------
__global__ void k_embed(const int* __restrict__ x, const float* __restrict__ emb) {
    int w = blockIdx.x * (blockDim.x >> 5) + (threadIdx.x >> 5);
    int lane = threadIdx.x & 31;
    if (w >= NROWS) return;
    const float* src = emb + (long)x[w] * EDIM;
    float v[10];
    float ss = 0.f;
    #pragma unroll
    for (int i = 0; i < 10; i++) {
        int c = lane + 32*i;
        float t = (c < EDIM) ? __ldg(src + c) : 0.f;
        v[i] = t; ss += t*t;
    }
    ss = warp_sum(ss);
    float sc = fminf(1.f, 5.f / (sqrtf(ss) + 1e-7f));
    float* dst = g_e + (long)w * EDIM;
    #pragma unroll
    for (int i = 0; i < 10; i++) {
        int c = lane + 32*i;
        if (c < EDIM) dst[c] = v[i] * sc;
    }
}

// ------------------------- K2: 128x128 FFMA2 GEMMs ---------------------------
#define GP 132
// NT: C[M,N] = A[M,K] . B[N,K]^T ; epi 0:+bias, 1:tanh(acc+tb2[(row>>8)*256+col]), 2:none
__global__ __launch_bounds__(256) void k_gemm_nt(
    const float* __restrict__ A, const float* __restrict__ B, float* __restrict__ C,
    int K, int lda, int ldb, int ldc, long sA, long sB, long sC,
    const float* __restrict__ bias, const float* __restrict__ tb2, int epi)
{
    __shared__ __align__(16) float As[16*GP];
    __shared__ __align__(16) float Bs[16*GP];
    int bz = blockIdx.z;
    A += sA * bz; B += sB * bz; C += sC * bz;
    int m0 = blockIdx.x << 7, n0 = blockIdx.y << 7;
    int tid = threadIdx.x;
    int tx = tid & 15, ty = tid >> 4;
    int srow = tid >> 1, skh = (tid & 1) << 3;
    const float* Ap = A + (long)(m0 + srow) * lda;
    const float* Bp = B + (long)(n0 + srow) * ldb;
    u64 acc[8][4] = {};
    for (int k0 = 0; k0 < K; k0 += 16) {
        if (k0 + 16 <= K) {
            float4 a0 = *(const float4*)(Ap + k0 + skh);
            float4 a1 = *(const float4*)(Ap + k0 + skh + 4);
            float4 b0 = *(const float4*)(Bp + k0 + skh);
            float4 b1 = *(const float4*)(Bp + k0 + skh + 4);
            As[(skh+0)*GP + srow] = a0.x; As[(skh+1)*GP + srow] = a0.y;
            As[(skh+2)*GP + srow] = a0.z; As[(skh+3)*GP + srow] = a0.w;
            As[(skh+4)*GP + srow] = a1.x; As[(skh+5)*GP + srow] = a1.y;
            As[(skh+6)*GP + srow] = a1.z; As[(skh+7)*GP + srow] = a1.w;
            Bs[(skh+0)*GP + srow] = b0.x; Bs[(skh+1)*GP + srow] = b0.y;
            Bs[(skh+2)*GP + srow] = b0.z; Bs[(skh+3)*GP + srow] = b0.w;
            Bs[(skh+4)*GP + srow] = b1.x; Bs[(skh+5)*GP + srow] = b1.y;
            Bs[(skh+6)*GP + srow] = b1.z; Bs[(skh+7)*GP + srow] = b1.w;
        } else {
            #pragma unroll
            for (int c = 0; c < 8; c++) {
                int kk = k0 + skh + c;
                As[(skh+c)*GP + srow] = (kk < K) ? Ap[kk] : 0.f;
                Bs[(skh+c)*GP + srow] = (kk < K) ? Bp[kk] : 0.f;
            }
        }
        __syncthreads();
        #pragma unroll
        for (int k = 0; k < 16; k++) {
            float a[8]; u64 bq[4];
            *(float4*)&a[0] = *(const float4*)&As[k*GP + (ty<<3)];
            *(float4*)&a[4] = *(const float4*)&As[k*GP + (ty<<3) + 4];
            ulonglong2 t0 = *(const ulonglong2*)&Bs[k*GP + (tx<<3)];
            ulonglong2 t1 = *(const ulonglong2*)&Bs[k*GP + (tx<<3) + 4];
            bq[0] = t0.x; bq[1] = t0.y; bq[2] = t1.x; bq[3] = t1.y;
            #pragma unroll
            for (int i = 0; i < 8; i++) {
                u64 ad = dup2(a[i]);
                acc[i][0] = fma2(ad, bq[0], acc[i][0]);
                acc[i][1] = fma2(ad, bq[1], acc[i][1]);
                acc[i][2] = fma2(ad, bq[2], acc[i][2]);
                acc[i][3] = fma2(ad, bq[3], acc[i][3]);
            }
        }
        __syncthreads();
    }
    #pragma unroll
    for (int i = 0; i < 8; i++) {
        int row = m0 + (ty << 3) + i;
        float v[8];
        #pragma unroll
        for (int p = 0; p < 4; p++) {
            float2 u = unpack2(acc[i][p]);
            v[2*p] = u.x; v[2*p+1] = u.y;
        }
        #pragma unroll
        for (int j = 0; j < 8; j++) {
            int col = n0 + (tx << 3) + j;
            if (epi == 0)      v[j] += bias[col];
            else if (epi == 1) v[j] = tanhf(v[j] + tb2[((row >> 8) << 8) + col]);
        }
        float* cp = C + (long)row * ldc + n0 + (tx << 3);
        *(float4*)cp       = make_float4(v[0], v[1], v[2], v[3]);
        *(float4*)(cp + 4) = make_float4(v[4], v[5], v[6], v[7]);
    }
}

// NN: C[M,N] = A[M,K] . B[K,N]  (K multiple of 16)
__global__ __launch_bounds__(256) void k_gemm_nn(
    const float* __restrict__ A, const float* __restrict__ B, float* __restrict__ C,
    int K, int lda, int ldb, int ldc, long sA, long sB, long sC)
{
    __shared__ __align__(16) float As[16*GP];
    __shared__ __align__(16) float Bs[16*GP];
    int bz = blockIdx.z;
    A += sA * bz; B += sB * bz; C += sC * bz;
    int m0 = blockIdx.x << 7, n0 = blockIdx.y << 7;
    int tid = threadIdx.x;
    int tx = tid & 15, ty = tid >> 4;
    int srow = tid >> 1, skh = (tid & 1) << 3;
    int bkk = tid >> 4, bc8 = (tid & 15) << 3;
    const float* Ap = A + (long)(m0 + srow) * lda;
    u64 acc[8][4] = {};
    for (int k0 = 0; k0 < K; k0 += 16) {
        {
            float4 a0 = *(const float4*)(Ap + k0 + skh);
            float4 a1 = *(const float4*)(Ap + k0 + skh + 4);
            As[(skh+0)*GP + srow] = a0.x; As[(skh+1)*GP + srow] = a0.y;
            As[(skh+2)*GP + srow] = a0.z; As[(skh+3)*GP + srow] = a0.w;
            As[(skh+4)*GP + srow] = a1.x; As[(skh+5)*GP + srow] = a1.y;
            As[(skh+6)*GP + srow] = a1.z; As[(skh+7)*GP + srow] = a1.w;
            const float* bp = B + (long)(k0 + bkk) * ldb + n0 + bc8;
            float4 b0 = *(const float4*)bp;
            float4 b1 = *(const float4*)(bp + 4);
            *(float4*)&Bs[bkk*GP + bc8]     = b0;
            *(float4*)&Bs[bkk*GP + bc8 + 4] = b1;
        }
        __syncthreads();
        #pragma unroll
        for (int k = 0; k < 16; k++) {
            float a[8]; u64 bq[4];
            *(float4*)&a[0] = *(const float4*)&As[k*GP + (ty<<3)];
            *(float4*)&a[4] = *(const float4*)&As[k*GP + (ty<<3) + 4];
            ulonglong2 t0 = *(const ulonglong2*)&Bs[k*GP + (tx<<3)];
            ulonglong2 t1 = *(const ulonglong2*)&Bs[k*GP + (tx<<3) + 4];
            bq[0] = t0.x; bq[1] = t0.y; bq[2] = t1.x; bq[3] = t1.y;
            #pragma unroll
            for (int i = 0; i < 8; i++) {
                u64 ad = dup2(a[i]);
                acc[i][0] = fma2(ad, bq[0], acc[i][0]);
                acc[i][1] = fma2(ad, bq[1], acc[i][1]);
                acc[i][2] = fma2(ad, bq[2], acc[i][2]);
                acc[i][3] = fma2(ad, bq[3], acc[i][3]);
            }
        }
        __syncthreads();
    }
    #pragma unroll
    for (int i = 0; i < 8; i++) {
        int row = m0 + (ty << 3) + i;
        float v[8];
        #pragma unroll
        for (int p = 0; p < 4; p++) {
            float2 u = unpack2(acc[i][p]);
            v[2*p] = u.x; v[2*p+1] = u.y;
        }
        float* cp = C + (long)row * ldc + n0 + (tx << 3);
        *(float4*)cp       = make_float4(v[0], v[1], v[2], v[3]);
        *(float4*)(cp + 4) = make_float4(v[4], v[5], v[6], v[7]);
    }
}

// ------------------------- K3: small split-K NT for target -------------------
__global__ __launch_bounds__(256) void k_gemm_target(
    const float* __restrict__ A, const float* __restrict__ B)
{
    __shared__ __align__(16) float As[16][64];
    __shared__ __align__(16) float Bs[16][64];
    int z = blockIdx.z;
    A += z * 128;      // lda 1024
    B += z * 128;      // ldb 2048
    float* C = g_tbp[z];
    int n0 = blockIdx.y << 6;
    int tid = threadIdx.x;
    int tx = tid & 15, ty = tid >> 4;
    float acc[4][4] = {};
    for (int k0 = 0; k0 < 128; k0 += 16) {
        int r = tid >> 2;
        int cb = (tid & 3) << 2;
        #pragma unroll
        for (int p = 0; p < 4; p++) {
            int c = cb + p;
            As[c][r] = A[(long)r * (2*HID) + k0 + c];
            Bs[c][r] = B[(long)(n0 + r) * (4*HID) + k0 + c];
        }
        __syncthreads();
        #pragma unroll
        for (int k = 0; k < 16; k++) {
            float4 av = *(const float4*)&As[k][ty << 2];
            float4 bv = *(const float4*)&Bs[k][tx << 2];
            float a[4] = {av.x, av.y, av.z, av.w};
            float b[4] = {bv.x, bv.y, bv.z, bv.w};
            #pragma unroll
            for (int i = 0; i < 4; i++)
                #pragma unroll
                for (int j = 0; j < 4; j++)
                    acc[i][j] = fmaf(a[i], b[j], acc[i][j]);
        }
        __syncthreads();
    }
    #pragma unroll
    for (int i = 0; i < 4; i++) {
        int row = (ty << 2) + i;
        #pragma unroll
        for (int j = 0; j < 4; j++)
            C[row * ATTD + n0 + (tx << 2) + j] = acc[i][j];
    }
}

__global__ void k_tb_reduce(const float* __restrict__ b1) {
    int i = blockIdx.x * blockDim.x + threadIdx.x;
    if (i >= BATCH * ATTD) return;
    float s = b1[i & (ATTD - 1)];
    #pragma unroll
    for (int z = 0; z < 8; z++) s += g_tbp[z][i];
    g_tb[i] = s;
}

// ------------------------- K4: persistent GRU v5 (k-split warps) -------------
// 128 blocks = 2 dir x 64 j-tiles(8 hidden units). 256 thr = 8 warps.
// Warp w owns k in [64w, 64w+64) and computes the FULL 24-row x 64-batch tile:
// lane (jq=lane>>3, bq=lane&7) tile = 2 j x 3 gates x 8 batches = 24 f32x2 acc.
// Per k per warp: 3 LDS.64 (W pairs) + 2 LDS.128 (h) = 14 crossbar-phases for
// 1536 FMA. 8-way k-split partials reduced through smem; gate epilogue per
// thread (j = tid>>5, batch-pair B = tid&31); leak h carried in registers.
// State layout plain [k][64b]; whole 128KB staged per step via one cp.async burst.
#define GRU_SMEM (48*1024 + 128*1024)
__global__ __launch_bounds__(256, 1) void k_gru_persistent(
    const float* __restrict__ Wf, const float* __restrict__ Wb,
    const float* __restrict__ bf, const float* __restrict__ bb)
{
    extern __shared__ __align__(16) float smem[];
    float* Wsm = smem;             // [k][24] : 512*24 floats = 48KB
    float* Hs  = smem + 512*24;    // [k][64] : 32768 floats = 128KB
    u64*   Ps  = (u64*)Hs;         // partial buffer (reuses Hs after matmul)

    int blk = blockIdx.x;
    int dir = blk >> 6;
    int j0  = (blk & 63) << 3;
    int tid = threadIdx.x;
    int w   = tid >> 5;
    int lane = tid & 31;
    int jq  = lane >> 3;          // 0..3  -> j pair {2jq, 2jq+1}
    int bq  = lane & 7;           // 0..7  -> batches [8bq, 8bq+8)

    const float* W  = dir ? Wb : Wf;
    const float* bh = dir ? bb : bf;

    // one-time W staging: Wsm[k*24 + g*8 + jj] = W[g*512 + j0 + jj][k]
    for (int r = 0; r < 24; r++) {
        int g = r >> 3, jj = r & 7;
        const float* wrow = W + (long)((g << 9) + j0 + jj) * HID;
        for (int k = tid; k < HID; k += 256)
            Wsm[k * 24 + r] = wrow[k];
    }
    __syncthreads();

    // epilogue mapping: thread = (j = tid>>5, B = tid&31 batch-pair)
    int ej  = tid >> 5;           // 0..7
    int eB  = tid & 31;           // 0..31 (batches 2eB, 2eB+1)
    int ejg = j0 + ej;
    float br = __ldg(&bh[ejg]);
    float bz = __ldg(&bh[HID + ejg]);
    float bn = __ldg(&bh[2*HID + ejg]);
    int elane = ((ej >> 1) << 3) | (eB >> 2);   // lane that produced this cell
    int eabase = (ej & 1) * 12 + (eB & 3);      // + g*4

    const float* xw = g_xw[dir];
    int b0 = eB << 1;
    long xrow0 = ((long)b0 * SEQ) * (3*HID);
    long xrow1 = ((long)(b0+1) * SEQ) * (3*HID);

    unsigned hs_base = smem_u32(Hs);
    int k0 = w << 6;
    int hoff = bq << 3;           // batch offset for this lane's h loads

    float hp0 = 0.f, hp1 = 0.f;   // leak state (register carried)

    for (int t = 0; t < SEQ; t++) {
        const float* sp = g_state[t & 1][dir];
        float*       sn = g_state[(t+1) & 1][dir];
        int tt = dir ? (SEQ-1-t) : t;

        // prefetch gate inputs (long latency, consumed in epilogue)
        long xo0 = xrow0 + (long)tt * (3*HID);
        long xo1 = xrow1 + (long)tt * (3*HID);
        float xr0 = __ldg(&xw[xo0 + ejg]);
        float xz0 = __ldg(&xw[xo0 + HID + ejg]);
        float xn0 = __ldg(&xw[xo0 + 2*HID + ejg]);
        float xr1 = __ldg(&xw[xo1 + ejg]);
        float xz1 = __ldg(&xw[xo1 + HID + ejg]);
        float xn1 = __ldg(&xw[xo1 + 2*HID + ejg]);

        // stage full state 128KB: 8192 float4, 32 per thread
        {
            const float4* sp4 = (const float4*)sp;
            #pragma unroll
            for (int p = 0; p < 32; p++) {
                int idx = tid + (p << 8);
                cpasync16(hs_base + ((unsigned)idx << 4), sp4 + idx);
            }
            asm volatile("cp.async.commit_group;" ::: "memory");
            asm volatile("cp.async.wait_group 0;" ::: "memory");
        }
        __syncthreads();

        // ---- matmul: warp w handles k in [k0, k0+64) ----
        u64 acc[2][3][4];
        #pragma unroll
        for (int a = 0; a < 2; a++)
            #pragma unroll
            for (int g = 0; g < 3; g++)
                #pragma unroll
                for (int p = 0; p < 4; p++) acc[a][g][p] = 0ull;

        #pragma unroll 4
        for (int kk = 0; kk < 64; kk++) {
            int k = k0 + kk;
            const float* hrow = Hs + (k << 6) + hoff;
            ulonglong2 hA = *(const ulonglong2*)hrow;        // batches 8bq..+3
            ulonglong2 hB = *(const ulonglong2*)(hrow + 4);  // batches 8bq+4..+7
            u64 hq[4] = {hA.x, hA.y, hB.x, hB.y};
            const float* wk = Wsm + k * 24 + (jq << 1);
            float2 wr = *(const float2*)(wk);        // gate r, j {2jq,2jq+1}
            float2 wz = *(const float2*)(wk + 8);
            float2 wn = *(const float2*)(wk + 16);
            u64 wd[2][3];
            wd[0][0] = dup2(wr.x); wd[1][0] = dup2(wr.y);
            wd[0][1] = dup2(wz.x); wd[1][1] = dup2(wz.y);
            wd[0][2] = dup2(wn.x); wd[1][2] = dup2(wn.y);
            #pragma unroll
            for (int a = 0; a < 2; a++)
                #pragma unroll
                for (int g = 0; g < 3; g++)
                    #pragma unroll
                    for (int p = 0; p < 4; p++)
                        acc[a][g][p] = fma2(wd[a][g], hq[p], acc[a][g][p]);
        }

        // ---- write k-split partials (Hs reuse; matmul reads done) ----
        __syncthreads();
        {
            u64* pb = Ps + ((w << 5) | lane) * 24;
            #pragma unroll
            for (int a = 0; a < 2; a++)
                #pragma unroll
                for (int g = 0; g < 3; g++)
                    #pragma unroll
                    for (int p = 0; p < 4; p++)
                        pb[a * 12 + g * 4 + p] = acc[a][g][p];
        }
        __syncthreads();

        // ---- reduce 8 partials + gate epilogue ----
        u64 s[3];
        #pragma unroll
        for (int g = 0; g < 3; g++) {
            int a = eabase + g * 4;
            u64 v = Ps[(elane) * 24 + a];
            #pragma unroll
            for (int ww = 1; ww < 8; ww++)
                v = add2(v, Ps[((ww << 5) | elane) * 24 + a]);
            s[g] = v;
        }
        float2 gr2 = unpack2(s[0]);
        float2 gz2 = unpack2(s[1]);
        float2 gn2 = unpack2(s[2]);

        float r0 = 1.f / (1.f + expf(-(xr0 + gr2.x + br)));
        float z0 = 1.f / (1.f + expf(-(xz0 + gz2.x + bz)));
        float n0 = tanhf(xn0 + r0 * (gn2.x + bn));
        float h0 = (1.f - z0) * n0 + z0 * hp0;
        float r1 = 1.f / (1.f + expf(-(xr1 + gr2.y + br)));
        float z1 = 1.f / (1.f + expf(-(xz1 + gz2.y + bz)));
        float n1 = tanhf(xn1 + r1 * (gn2.y + bn));
        float h1 = (1.f - z1) * n1 + z1 * hp1;
        hp0 = h0; hp1 = h1;

        ((float2*)sn)[ejg * 32 + eB] = make_float2(h0, h1);
        g_h[((long)b0*SEQ + tt) * (2*HID) + dir*HID + ejg] = h0;
        g_h[((long)(b0+1)*SEQ + tt) * (2*HID) + dir*HID + ejg] = h1;

        // ---- grid barrier ----
        if (t < SEQ - 1) {
            __syncthreads();
            if (tid == 0) {
                __threadfence();
                unsigned a = atomicAdd(&g_bar_cnt, 1u);
                if (a == GRU_BLOCKS - 1) {
                    g_bar_cnt = 0u;
                    __threadfence();
                    g_bar_gen = (unsigned)(t + 1);
                } else {
                    while (g_bar_gen < (unsigned)(t + 1)) { }
                }
            }
            __syncthreads();
        }
    }
}

// ------------------------- K5: masked mean pooling ---------------------------
__global__ void k_pool(const int* __restrict__ ts, const int* __restrict__ te) {
    int b = blockIdx.x;
    int s0 = ts[b], s1 = te[b];
    float inv = 1.f / (float)(s1 - s0 + 1);
    for (int c = threadIdx.x; c < 2*HID; c += blockDim.x) {
        float a = 0.f;
        for (int s = s0; s <= s1; s++)
            a += g_h[((long)b * SEQ + s) * (2*HID) + c];
        g_target[b * 2*HID + c] = a * inv;
    }
}

// ------------------------- K8: row softmax over S ----------------------------
__global__ void k_softmax() {
    int row = blockIdx.x * (blockDim.x >> 5) + (threadIdx.x >> 5);
    int lane = threadIdx.x & 31;
    float* p = g_alfa + (long)row * SEQ;
    float v[8];
    float mx = -1e30f;
    #pragma unroll
    for (int i = 0; i < 8; i++) { v[i] = p[lane + 32*i]; mx = fmaxf(mx, v[i]); }
    mx = warp_max(mx);
    float s = 0.f;
    #pragma unroll
    for (int i = 0; i < 8; i++) { v[i] = expf(v[i] - mx); s += v[i]; }
    s = warp_sum(s);
    float inv = 1.f / s;
    #pragma unroll
    for (int i = 0; i < 8; i++) p[lane + 32*i] = v[i] * inv;
}

// ------------------------- K10: result @ W2^T + b2 ---------------------------
__global__ void k_final(const float* __restrict__ W2, const float* __restrict__ b2,
                        float* __restrict__ out) {
    int row = blockIdx.x * 8 + (threadIdx.x >> 5);
    int lane = threadIdx.x & 31;
    const float* R = g_att + (long)row * (2*HID);
    float a0 = 0.f, a1 = 0.f, a2 = 0.f;
    for (int h = lane; h < 2*HID; h += 32) {
        float r = R[h];
        a0 = fmaf(r, W2[h],           a0);
        a1 = fmaf(r, W2[2*HID + h],   a1);
        a2 = fmaf(r, W2[4*HID + h],   a2);
    }
    a0 = warp_sum(a0); a1 = warp_sum(a1); a2 = warp_sum(a2);
    if (lane == 0) {
        out[row*3 + 0] = a0 + b2[0];
        out[row*3 + 1] = a1 + b2[1];
        out[row*3 + 2] = a2 + b2[2];
    }
}

// ------------------------- launcher ------------------------------------------
extern "C" void kernel_launch(void* const* d_in, const int* in_sizes, int n_in,
                              void* d_out, int out_size) {
    const int*   x      = (const int*)  d_in[0];
    const int*   tstart = (const int*)  d_in[1];
    const int*   tend   = (const int*)  d_in[2];
    const float* emb    = (const float*)d_in[3];
    const float* Wih_f  = (const float*)d_in[4];
    const float* Whh_f  = (const float*)d_in[5];
    const float* bih_f  = (const float*)d_in[6];
    const float* bhh_f  = (const float*)d_in[7];
    const float* Wih_b  = (const float*)d_in[8];
    const float* Whh_b  = (const float*)d_in[9];
    const float* bih_b  = (const float*)d_in[10];
    const float* bhh_b  = (const float*)d_in[11];
    const float* W1     = (const float*)d_in[12];
    const float* b1     = (const float*)d_in[13];
    const float* u      = (const float*)d_in[14];
    const float* W2     = (const float*)d_in[15];
    const float* b2     = (const float*)d_in[16];
    float* out = (float*)d_out;

    static int smem_set = 0;
    if (!smem_set) {
        cudaFuncSetAttribute(k_gru_persistent,
                             cudaFuncAttributeMaxDynamicSharedMemorySize, GRU_SMEM);
        smem_set = 1;
    }

    float *p_e, *p_xw, *p_h, *p_target, *p_tb, *p_o, *p_alfa, *p_att;
    cudaGetSymbolAddress((void**)&p_e,      g_e);
    cudaGetSymbolAddress((void**)&p_xw,     g_xw);
    cudaGetSymbolAddress((void**)&p_h,      g_h);
    cudaGetSymbolAddress((void**)&p_target, g_target);
    cudaGetSymbolAddress((void**)&p_tb,     g_tb);
    cudaGetSymbolAddress((void**)&p_o,      g_o);
    cudaGetSymbolAddress((void**)&p_alfa,   g_alfa);
    cudaGetSymbolAddress((void**)&p_att,    g_att);
    float* p_xw0 = p_xw;
    float* p_xw1 = p_xw + (long)NROWS * 3 * HID;

    k_zero_state<<<512, 256>>>();
    k_embed<<<2048, 256>>>(x, emb);

    // input projections: [16384,300] x [1536,300]^T (+bih)
    k_gemm_nt<<<dim3(128, 12, 1), 256>>>(p_e, Wih_f, p_xw0, EDIM,
                                         EDIM, EDIM, 3*HID, 0, 0, 0,
                                         bih_f, nullptr, 0);
    k_gemm_nt<<<dim3(128, 12, 1), 256>>>(p_e, Wih_b, p_xw1, EDIM,
                                         EDIM, EDIM, 3*HID, 0, 0, 0,
                                         bih_b, nullptr, 0);

    // full recurrence in ONE persistent kernel
    k_gru_persistent<<<GRU_BLOCKS, 256, GRU_SMEM>>>(Whh_f, Whh_b, bhh_f, bhh_b);

    // masked mean pool over target span
    k_pool<<<64, 256>>>(tstart, tend);

    // tb = target . W1[:,1024:]^T + b1  (split-K 8 + reduce)
    k_gemm_target<<<dim3(1, 4, 8), 256>>>(p_target, W1 + 1024);
    k_tb_reduce<<<64, 256>>>(b1);

    // o = tanh(h . W1[:,:1024]^T + tb[b])   (M=16384,N=256,K=1024)
    k_gemm_nt<<<dim3(128, 2, 1), 256>>>(p_h, W1, p_o, 2*HID,
                                        2*HID, 4*HID, ATTD, 0, 0, 0,
                                        nullptr, p_tb, 1);

    // beta[b,k,s] = u[k] . o[b,s]           (batched NT, 256x256x256)
    k_gemm_nt<<<dim3(2, 2, 64), 256>>>(u, p_o, p_alfa, ATTD,
                                       ATTD, ATTD, SEQ,
                                       0, (long)SEQ*ATTD, (long)ATTD*SEQ,
                                       nullptr, nullptr, 2);

    // softmax over s
    k_softmax<<<2048, 256>>>();

    // result[b,k,:] = alfa[b,k,:] . h[b]    (batched NN, 256x1024x256)
    k_gemm_nn<<<dim3(2, 8, 64), 256>>>(p_alfa, p_h, p_att, SEQ,
                                       SEQ, 2*HID, 2*HID,
                                       (long)ATTD*SEQ, (long)SEQ*2*HID,
                                       (long)ATTD*2*HID);

    // final projection to 3 labels
    k_final<<<2048, 256>>>(W2, b2, out);
}

// round 11
// speedup vs baseline: 1.9195x; 1.0087x over previous
#include <cuda_runtime.h>
#include <math.h>

#define BATCH 64
#define SEQ   256
#define EDIM  300
#define HID   512
#define ATTD  256
#define NROWS (BATCH*SEQ)          // 16384
#define GRU_BLOCKS 128

typedef unsigned long long u64;

// ------------------------- scratch (static device memory) -------------------
__device__ float g_e[NROWS*EDIM];              // renormed embeddings  [16384,300]
__device__ float g_xw[2][NROWS*3*HID];         // input projections    [dir][b*256+s][1536]
__device__ float g_h[NROWS*2*HID];             // concat hidden        [b,s,1024]
__device__ float g_state[2][2][HID*BATCH];     // [parity][dir][k][64b]  plain layout
__device__ float g_target[BATCH*2*HID];        // pooled target        [64,1024]
__device__ float g_tbp[8][BATCH*ATTD];         // split-K partials
__device__ float g_tb[BATCH*ATTD];             // target@W1b + b1      [64,256]
__device__ float g_o[NROWS*ATTD];              // tanh attention feats [16384,256]
__device__ float g_alfa[BATCH*ATTD*SEQ];       // beta -> alfa         [64,256,256]
__device__ float g_att[NROWS*2*HID];           // result               [b*256+k,1024]

__device__ volatile unsigned g_bar_gen;
__device__ unsigned g_bar_cnt;

// ------------------------- helpers -------------------------------------------
__device__ __forceinline__ u64 dup2(float w) {
    u64 r; asm("mov.b64 %0, {%1, %1};" : "=l"(r) : "f"(w)); return r;
}
__device__ __forceinline__ u64 fma2(u64 a, u64 b, u64 c) {
    u64 d; asm("fma.rn.f32x2 %0, %1, %2, %3;" : "=l"(d) : "l"(a), "l"(b), "l"(c));
    return d;
}
__device__ __forceinline__ u64 add2(u64 a, u64 b) {
    u64 d; asm("add.rn.f32x2 %0, %1, %2;" : "=l"(d) : "l"(a), "l"(b));
    return d;
}
__device__ __forceinline__ float2 unpack2(u64 v) {
    float2 f; asm("mov.b64 {%0, %1}, %2;" : "=f"(f.x), "=f"(f.y) : "l"(v)); return f;
}
__device__ __forceinline__ unsigned smem_u32(const void* p) {
    unsigned a;
    asm("{ .reg .u64 t; cvta.to.shared.u64 t, %1; cvt.u32.u64 %0, t; }"
        : "=r"(a) : "l"(p));
    return a;
}
__device__ __forceinline__ void cpasync16(unsigned s, const void* g) {
    asm volatile("cp.async.cg.shared.global [%0], [%1], 16;" :: "r"(s), "l"(g));
}
__device__ __forceinline__ float warp_sum(float v) {
    #pragma unroll
    for (int o = 16; o > 0; o >>= 1) v += __shfl_xor_sync(0xffffffffu, v, o);
    return v;
}
__device__ __forceinline__ float warp_max(float v) {
    #pragma unroll
    for (int o = 16; o > 0; o >>= 1) v = fmaxf(v, __shfl_xor_sync(0xffffffffu, v, o));
    return v;
}

// ------------------------- K0: zero GRU state + barrier ----------------------
__global__ void k_zero_state() {
    int i = blockIdx.x * blockDim.x + threadIdx.x;
    if (i < 2*2*HID*BATCH) ((float*)g_state)[i] = 0.f;
    if (i == 0) { g_bar_gen = 0u; g_bar_cnt = 0u; }
}

// ------------------------- K1: embedding gather + renorm ---------------------
__global__ void k_embed(const int* __restrict__ x, const float* __restrict__ emb) {
    int w = blockIdx.x * (blockDim.x >> 5) + (threadIdx.x >> 5);
    int lane = threadIdx.x & 31;
    if (w >= NROWS) return;
    const float* src = emb + (long)x[w] * EDIM;
    float v[10];
    float ss = 0.f;
    #pragma unroll
    for (int i = 0; i < 10; i++) {
        int c = lane + 32*i;
        float t = (c < EDIM) ? __ldg(src + c) : 0.f;
        v[i] = t; ss += t*t;
    }
    ss = warp_sum(ss);
    float sc = fminf(1.f, 5.f / (sqrtf(ss) + 1e-7f));
    float* dst = g_e + (long)w * EDIM;
    #pragma unroll
    for (int i = 0; i < 10; i++) {
        int c = lane + 32*i;
        if (c < EDIM) dst[c] = v[i] * sc;
    }
}

// ------------------------- K2: 128x128 FFMA2 GEMMs, 32-k tiles ---------------
#define GP 132
// NT: C[M,N] = A[M,K] . B[N,K]^T ; epi 0:+bias, 1:tanh(acc+tb2[(row>>8)*256+col]), 2:none
__global__ __launch_bounds__(256) void k_gemm_nt(
    const float* __restrict__ A, const float* __restrict__ B, float* __restrict__ C,
    int K, int lda, int ldb, int ldc, long sA, long sB, long sC,
    const float* __restrict__ bias, const float* __restrict__ tb2, int epi)
{
    __shared__ __align__(16) float As[32*GP];
    __shared__ __align__(16) float Bs[32*GP];
    int bz = blockIdx.z;
    A += sA * bz; B += sB * bz; C += sC * bz;
    int m0 = blockIdx.x << 7, n0 = blockIdx.y << 7;
    int tid = threadIdx.x;
    int tx = tid & 15, ty = tid >> 4;
    int srow = tid >> 1, skh = (tid & 1) << 4;     // 16 k per thread
    const float* Ap = A + (long)(m0 + srow) * lda;
    const float* Bp = B + (long)(n0 + srow) * ldb;
    u64 acc[8][4] = {};
    for (int k0 = 0; k0 < K; k0 += 32) {
        if (k0 + 32 <= K) {
            #pragma unroll
            for (int q = 0; q < 4; q++) {
                float4 a = *(const float4*)(Ap + k0 + skh + (q << 2));
                float4 b = *(const float4*)(Bp + k0 + skh + (q << 2));
                int c = skh + (q << 2);
                As[(c+0)*GP + srow] = a.x; As[(c+1)*GP + srow] = a.y;
                As[(c+2)*GP + srow] = a.z; As[(c+3)*GP + srow] = a.w;
                Bs[(c+0)*GP + srow] = b.x; Bs[(c+1)*GP + srow] = b.y;
                Bs[(c+2)*GP + srow] = b.z; Bs[(c+3)*GP + srow] = b.w;
            }
        } else {
            #pragma unroll
            for (int c = 0; c < 16; c++) {
                int kk = k0 + skh + c;
                As[(skh+c)*GP + srow] = (kk < K) ? Ap[kk] : 0.f;
                Bs[(skh+c)*GP + srow] = (kk < K) ? Bp[kk] : 0.f;
            }
        }
        __syncthreads();
        #pragma unroll
        for (int k = 0; k < 32; k++) {
            float a[8]; u64 bq[4];
            *(float4*)&a[0] = *(const float4*)&As[k*GP + (ty<<3)];
            *(float4*)&a[4] = *(const float4*)&As[k*GP + (ty<<3) + 4];
            ulonglong2 t0 = *(const ulonglong2*)&Bs[k*GP + (tx<<3)];
            ulonglong2 t1 = *(const ulonglong2*)&Bs[k*GP + (tx<<3) + 4];
            bq[0] = t0.x; bq[1] = t0.y; bq[2] = t1.x; bq[3] = t1.y;
            #pragma unroll
            for (int i = 0; i < 8; i++) {
                u64 ad = dup2(a[i]);
                acc[i][0] = fma2(ad, bq[0], acc[i][0]);
                acc[i][1] = fma2(ad, bq[1], acc[i][1]);
                acc[i][2] = fma2(ad, bq[2], acc[i][2]);
                acc[i][3] = fma2(ad, bq[3], acc[i][3]);
            }
        }
        __syncthreads();
    }
    #pragma unroll
    for (int i = 0; i < 8; i++) {
        int row = m0 + (ty << 3) + i;
        float v[8];
        #pragma unroll
        for (int p = 0; p < 4; p++) {
            float2 u = unpack2(acc[i][p]);
            v[2*p] = u.x; v[2*p+1] = u.y;
        }
        #pragma unroll
        for (int j = 0; j < 8; j++) {
            int col = n0 + (tx << 3) + j;
            if (epi == 0)      v[j] += bias[col];
            else if (epi == 1) v[j] = tanhf(v[j] + tb2[((row >> 8) << 8) + col]);
        }
        float* cp = C + (long)row * ldc + n0 + (tx << 3);
        *(float4*)cp       = make_float4(v[0], v[1], v[2], v[3]);
        *(float4*)(cp + 4) = make_float4(v[4], v[5], v[6], v[7]);
    }
}

// NN: C[M,N] = A[M,K] . B[K,N]  (K multiple of 32)
__global__ __launch_bounds__(256) void k_gemm_nn(
    const float* __restrict__ A, const float* __restrict__ B, float* __restrict__ C,
    int K, int lda, int ldb, int ldc, long sA, long sB, long sC)
{
    __shared__ __align__(16) float As[32*GP];
    __shared__ __align__(16) float Bs[32*GP];
    int bz = blockIdx.z;
    A += sA * bz; B += sB * bz; C += sC * bz;
    int m0 = blockIdx.x << 7, n0 = blockIdx.y << 7;
    int tid = threadIdx.x;
    int tx = tid & 15, ty = tid >> 4;
    int srow = tid >> 1, skh = (tid & 1) << 4;
    int bkk = tid >> 4, bc8 = (tid & 15) << 3;
    const float* Ap = A + (long)(m0 + srow) * lda;
    u64 acc[8][4] = {};
    for (int k0 = 0; k0 < K; k0 += 32) {
        {
            #pragma unroll
            for (int q = 0; q < 4; q++) {
                float4 a = *(const float4*)(Ap + k0 + skh + (q << 2));
                int c = skh + (q << 2);
                As[(c+0)*GP + srow] = a.x; As[(c+1)*GP + srow] = a.y;
                As[(c+2)*GP + srow] = a.z; As[(c+3)*GP + srow] = a.w;
            }
            #pragma unroll
            for (int h = 0; h < 2; h++) {
                int kk = bkk + (h << 4);
                const float* bp = B + (long)(k0 + kk) * ldb + n0 + bc8;
                float4 b0 = *(const float4*)bp;
                float4 b1 = *(const float4*)(bp + 4);
                *(float4*)&Bs[kk*GP + bc8]     = b0;
                *(float4*)&Bs[kk*GP + bc8 + 4] = b1;
            }
        }
        __syncthreads();
        #pragma unroll
        for (int k = 0; k < 32; k++) {
            float a[8]; u64 bq[4];
            *(float4*)&a[0] = *(const float4*)&As[k*GP + (ty<<3)];
            *(float4*)&a[4] = *(const float4*)&As[k*GP + (ty<<3) + 4];
            ulonglong2 t0 = *(const ulonglong2*)&Bs[k*GP + (tx<<3)];
            ulonglong2 t1 = *(const ulonglong2*)&Bs[k*GP + (tx<<3) + 4];
            bq[0] = t0.x; bq[1] = t0.y; bq[2] = t1.x; bq[3] = t1.y;
            #pragma unroll
            for (int i = 0; i < 8; i++) {
                u64 ad = dup2(a[i]);
                acc[i][0] = fma2(ad, bq[0], acc[i][0]);
                acc[i][1] = fma2(ad, bq[1], acc[i][1]);
                acc[i][2] = fma2(ad, bq[2], acc[i][2]);
                acc[i][3] = fma2(ad, bq[3], acc[i][3]);
            }
        }
        __syncthreads();
    }
    #pragma unroll
    for (int i = 0; i < 8; i++) {
        int row = m0 + (ty << 3) + i;
        float v[8];
        #pragma unroll
        for (int p = 0; p < 4; p++) {
            float2 u = unpack2(acc[i][p]);
            v[2*p] = u.x; v[2*p+1] = u.y;
        }
        float* cp = C + (long)row * ldc + n0 + (tx << 3);
        *(float4*)cp       = make_float4(v[0], v[1], v[2], v[3]);
        *(float4*)(cp + 4) = make_float4(v[4], v[5], v[6], v[7]);
    }
}

// ------------------------- K3: small split-K NT for target -------------------
__global__ __launch_bounds__(256) void k_gemm_target(
    const float* __restrict__ A, const float* __restrict__ B)
{
    __shared__ __align__(16) float As[16][64];
    __shared__ __align__(16) float Bs[16][64];
    int z = blockIdx.z;
    A += z * 128;      // lda 1024
    B += z * 128;      // ldb 2048
    float* C = g_tbp[z];
    int n0 = blockIdx.y << 6;
    int tid = threadIdx.x;
    int tx = tid & 15, ty = tid >> 4;
    float acc[4][4] = {};
    for (int k0 = 0; k0 < 128; k0 += 16) {
        int r = tid >> 2;
        int cb = (tid & 3) << 2;
        #pragma unroll
        for (int p = 0; p < 4; p++) {
            int c = cb + p;
            As[c][r] = A[(long)r * (2*HID) + k0 + c];
            Bs[c][r] = B[(long)(n0 + r) * (4*HID) + k0 + c];
        }
        __syncthreads();
        #pragma unroll
        for (int k = 0; k < 16; k++) {
            float4 av = *(const float4*)&As[k][ty << 2];
            float4 bv = *(const float4*)&Bs[k][tx << 2];
            float a[4] = {av.x, av.y, av.z, av.w};
            float b[4] = {bv.x, bv.y, bv.z, bv.w};
            #pragma unroll
            for (int i = 0; i < 4; i++)
                #pragma unroll
                for (int j = 0; j < 4; j++)
                    acc[i][j] = fmaf(a[i], b[j], acc[i][j]);
        }
        __syncthreads();
    }
    #pragma unroll
    for (int i = 0; i < 4; i++) {
        int row = (ty << 2) + i;
        #pragma unroll
        for (int j = 0; j < 4; j++)
            C[row * ATTD + n0 + (tx << 2) + j] = acc[i][j];
    }
}

__global__ void k_tb_reduce(const float* __restrict__ b1) {
    int i = blockIdx.x * blockDim.x + threadIdx.x;
    if (i >= BATCH * ATTD) return;
    float s = b1[i & (ATTD - 1)];
    #pragma unroll
    for (int z = 0; z < 8; z++) s += g_tbp[z][i];
    g_tb[i] = s;
}

// ------------------------- K4: persistent GRU v6 (per-warp staging) ----------
// Same k-split decomposition as v5, but each warp stages ONLY its own 64-k slab
// (16KB) with its own cp.async group and waits only that group + __syncwarp.
// No block-wide sync between staging and matmul; warps' staging overlaps other
// warps' compute naturally.
#define GRU_SMEM (48*1024 + 128*1024)
__global__ __launch_bounds__(256, 1) void k_gru_persistent(
    const float* __restrict__ Wf, const float* __restrict__ Wb,
    const float* __restrict__ bf, const float* __restrict__ bb)
{
    extern __shared__ __align__(16) float smem[];
    float* Wsm = smem;             // [k][24] : 512*24 floats = 48KB
    float* Hs  = smem + 512*24;    // [k][64] : 32768 floats = 128KB
    u64*   Ps  = (u64*)Hs;         // partial buffer (reuses Hs after matmul)

    int blk = blockIdx.x;
    int dir = blk >> 6;
    int j0  = (blk & 63) << 3;
    int tid = threadIdx.x;
    int w   = tid >> 5;
    int lane = tid & 31;
    int jq  = lane >> 3;          // 0..3  -> j pair {2jq, 2jq+1}
    int bq  = lane & 7;           // 0..7  -> batches [8bq, 8bq+8)

    const float* W  = dir ? Wb : Wf;
    const float* bh = dir ? bb : bf;

    // one-time W staging: Wsm[k*24 + g*8 + jj] = W[g*512 + j0 + jj][k]
    for (int r = 0; r < 24; r++) {
        int g = r >> 3, jj = r & 7;
        const float* wrow = W + (long)((g << 9) + j0 + jj) * HID;
        for (int k = tid; k < HID; k += 256)
            Wsm[k * 24 + r] = wrow[k];
    }
    __syncthreads();

    // epilogue mapping: thread = (j = tid>>5, B = tid&31 batch-pair)
    int ej  = tid >> 5;           // 0..7
    int eB  = tid & 31;           // 0..31 (batches 2eB, 2eB+1)
    int ejg = j0 + ej;
    float br = __ldg(&bh[ejg]);
    float bz = __ldg(&bh[HID + ejg]);
    float bn = __ldg(&bh[2*HID + ejg]);
    int elane = ((ej >> 1) << 3) | (eB >> 2);   // lane that produced this cell
    int eabase = (ej & 1) * 12 + (eB & 3);      // + g*4

    const float* xw = g_xw[dir];
    int b0 = eB << 1;
    long xrow0 = ((long)b0 * SEQ) * (3*HID);
    long xrow1 = ((long)(b0+1) * SEQ) * (3*HID);

    unsigned hs_base = smem_u32(Hs);
    int k0 = w << 6;
    int hoff = bq << 3;           // batch offset for this lane's h loads
    int slab4 = k0 << 4;          // first float4 index of this warp's slab

    float hp0 = 0.f, hp1 = 0.f;   // leak state (register carried)

    for (int t = 0; t < SEQ; t++) {
        const float* sp = g_state[t & 1][dir];
        float*       sn = g_state[(t+1) & 1][dir];
        int tt = dir ? (SEQ-1-t) : t;

        // stage OWN slab first (fire before the xw prefetch so copies overlap it)
        {
            const float4* sp4 = (const float4*)sp;
            #pragma unroll
            for (int p = 0; p < 32; p++) {
                int idx = slab4 + lane + (p << 5);
                cpasync16(hs_base + ((unsigned)idx << 4), sp4 + idx);
            }
            asm volatile("cp.async.commit_group;" ::: "memory");
        }

        // gate-input prefetch (long latency, consumed in epilogue)
        long xo0 = xrow0 + (long)tt * (3*HID);
        long xo1 = xrow1 + (long)tt * (3*HID);
        float xr0 = __ldg(&xw[xo0 + ejg]);
        float xz0 = __ldg(&xw[xo0 + HID + ejg]);
        float xn0 = __ldg(&xw[xo0 + 2*HID + ejg]);
        float xr1 = __ldg(&xw[xo1 + ejg]);
        float xz1 = __ldg(&xw[xo1 + HID + ejg]);
        float xn1 = __ldg(&xw[xo1 + 2*HID + ejg]);

        asm volatile("cp.async.wait_group 0;" ::: "memory");
        __syncwarp();

        // ---- matmul: warp w handles k in [k0, k0+64) ----
        u64 acc[2][3][4];
        #pragma unroll
        for (int a = 0; a < 2; a++)
            #pragma unroll
            for (int g = 0; g < 3; g++)
                #pragma unroll
                for (int p = 0; p < 4; p++) acc[a][g][p] = 0ull;

        #pragma unroll 4
        for (int kk = 0; kk < 64; kk++) {
            int k = k0 + kk;
            const float* hrow = Hs + (k << 6) + hoff;
            ulonglong2 hA = *(const ulonglong2*)hrow;        // batches 8bq..+3
            ulonglong2 hB = *(const ulonglong2*)(hrow + 4);  // batches 8bq+4..+7
            u64 hq[4] = {hA.x, hA.y, hB.x, hB.y};
            const float* wk = Wsm + k * 24 + (jq << 1);
            float2 wr = *(const float2*)(wk);        // gate r, j {2jq,2jq+1}
            float2 wz = *(const float2*)(wk + 8);
            float2 wn = *(const float2*)(wk + 16);
            u64 wd[2][3];
            wd[0][0] = dup2(wr.x); wd[1][0] = dup2(wr.y);
            wd[0][1] = dup2(wz.x); wd[1][1] = dup2(wz.y);
            wd[0][2] = dup2(wn.x); wd[1][2] = dup2(wn.y);
            #pragma unroll
            for (int a = 0; a < 2; a++)
                #pragma unroll
                for (int g = 0; g < 3; g++)
                    #pragma unroll
                    for (int p = 0; p < 4; p++)
                        acc[a][g][p] = fma2(wd[a][g], hq[p], acc[a][g][p]);
        }

        // ---- write k-split partials (Hs reuse; all matmul reads done) ----
        __syncthreads();
        {
            u64* pb = Ps + ((w << 5) | lane) * 24;
            #pragma unroll
            for (int a = 0; a < 2; a++)
                #pragma unroll
                for (int g = 0; g < 3; g++)
                    #pragma unroll
                    for (int p = 0; p < 4; p++)
                        pb[a * 12 + g * 4 + p] = acc[a][g][p];
        }
        __syncthreads();

        // ---- reduce 8 partials + gate epilogue ----
        u64 s[3];
        #pragma unroll
        for (int g = 0; g < 3; g++) {
            int a = eabase + g * 4;
            u64 v = Ps[(elane) * 24 + a];
            #pragma unroll
            for (int ww = 1; ww < 8; ww++)
                v = add2(v, Ps[((ww << 5) | elane) * 24 + a]);
            s[g] = v;
        }
        float2 gr2 = unpack2(s[0]);
        float2 gz2 = unpack2(s[1]);
        float2 gn2 = unpack2(s[2]);

        float r0 = 1.f / (1.f + expf(-(xr0 + gr2.x + br)));
        float z0 = 1.f / (1.f + expf(-(xz0 + gz2.x + bz)));
        float n0 = tanhf(xn0 + r0 * (gn2.x + bn));
        float h0 = (1.f - z0) * n0 + z0 * hp0;
        float r1 = 1.f / (1.f + expf(-(xr1 + gr2.y + br)));
        float z1 = 1.f / (1.f + expf(-(xz1 + gz2.y + bz)));
        float n1 = tanhf(xn1 + r1 * (gn2.y + bn));
        float h1 = (1.f - z1) * n1 + z1 * hp1;
        hp0 = h0; hp1 = h1;

        ((float2*)sn)[ejg * 32 + eB] = make_float2(h0, h1);
        g_h[((long)b0*SEQ + tt) * (2*HID) + dir*HID + ejg] = h0;
        g_h[((long)(b0+1)*SEQ + tt) * (2*HID) + dir*HID + ejg] = h1;

        // ---- grid barrier ----
        if (t < SEQ - 1) {
            __syncthreads();
            if (tid == 0) {
                __threadfence();
                unsigned a = atomicAdd(&g_bar_cnt, 1u);
                if (a == GRU_BLOCKS - 1) {
                    g_bar_cnt = 0u;
                    __threadfence();
                    g_bar_gen = (unsigned)(t + 1);
                } else {
                    while (g_bar_gen < (unsigned)(t + 1)) { }
                }
            }
            __syncthreads();
        }
    }
}

// ------------------------- K5: masked mean pooling ---------------------------
__global__ void k_pool(const int* __restrict__ ts, const int* __restrict__ te) {
    int b = blockIdx.x;
    int s0 = ts[b], s1 = te[b];
    float inv = 1.f / (float)(s1 - s0 + 1);
    for (int c = threadIdx.x; c < 2*HID; c += blockDim.x) {
        float a = 0.f;
        for (int s = s0; s <= s1; s++)
            a += g_h[((long)b * SEQ + s) * (2*HID) + c];
        g_target[b * 2*HID + c] = a * inv;
    }
}

// ------------------------- K8: row softmax over S ----------------------------
__global__ void k_softmax() {
    int row = blockIdx.x * (blockDim.x >> 5) + (threadIdx.x >> 5);
    int lane = threadIdx.x & 31;
    float* p = g_alfa + (long)row * SEQ;
    float v[8];
    float mx = -1e30f;
    #pragma unroll
    for (int i = 0; i < 8; i++) { v[i] = p[lane + 32*i]; mx = fmaxf(mx, v[i]); }
    mx = warp_max(mx);
    float s = 0.f;
    #pragma unroll
    for (int i = 0; i < 8; i++) { v[i] = expf(v[i] - mx); s += v[i]; }
    s = warp_sum(s);
    float inv = 1.f / s;
    #pragma unroll
    for (int i = 0; i < 8; i++) p[lane + 32*i] = v[i] * inv;
}

// ------------------------- K10: result @ W2^T + b2 ---------------------------
__global__ void k_final(const float* __restrict__ W2, const float* __restrict__ b2,
                        float* __restrict__ out) {
    int row = blockIdx.x * 8 + (threadIdx.x >> 5);
    int lane = threadIdx.x & 31;
    const float* R = g_att + (long)row * (2*HID);
    float a0 = 0.f, a1 = 0.f, a2 = 0.f;
    for (int h = lane; h < 2*HID; h += 32) {
        float r = R[h];
        a0 = fmaf(r, W2[h],           a0);
        a1 = fmaf(r, W2[2*HID + h],   a1);
        a2 = fmaf(r, W2[4*HID + h],   a2);
    }
    a0 = warp_sum(a0); a1 = warp_sum(a1); a2 = warp_sum(a2);
    if (lane == 0) {
        out[row*3 + 0] = a0 + b2[0];
        out[row*3 + 1] = a1 + b2[1];
        out[row*3 + 2] = a2 + b2[2];
    }
}

// ------------------------- launcher ------------------------------------------
extern "C" void kernel_launch(void* const* d_in, const int* in_sizes, int n_in,
                              void* d_out, int out_size) {
    const int*   x      = (const int*)  d_in[0];
    const int*   tstart = (const int*)  d_in[1];
    const int*   tend   = (const int*)  d_in[2];
    const float* emb    = (const float*)d_in[3];
    const float* Wih_f  = (const float*)d_in[4];
    const float* Whh_f  = (const float*)d_in[5];
    const float* bih_f  = (const float*)d_in[6];
    const float* bhh_f  = (const float*)d_in[7];
    const float* Wih_b  = (const float*)d_in[8];
    const float* Whh_b  = (const float*)d_in[9];
    const float* bih_b  = (const float*)d_in[10];
    const float* bhh_b  = (const float*)d_in[11];
    const float* W1     = (const float*)d_in[12];
    const float* b1     = (const float*)d_in[13];
    const float* u      = (const float*)d_in[14];
    const float* W2     = (const float*)d_in[15];
    const float* b2     = (const float*)d_in[16];
    float* out = (float*)d_out;

    static int smem_set = 0;
    if (!smem_set) {
        cudaFuncSetAttribute(k_gru_persistent,
                             cudaFuncAttributeMaxDynamicSharedMemorySize, GRU_SMEM);
        smem_set = 1;
    }

    float *p_e, *p_xw, *p_h, *p_target, *p_tb, *p_o, *p_alfa, *p_att;
    cudaGetSymbolAddress((void**)&p_e,      g_e);
    cudaGetSymbolAddress((void**)&p_xw,     g_xw);
    cudaGetSymbolAddress((void**)&p_h,      g_h);
    cudaGetSymbolAddress((void**)&p_target, g_target);
    cudaGetSymbolAddress((void**)&p_tb,     g_tb);
    cudaGetSymbolAddress((void**)&p_o,      g_o);
    cudaGetSymbolAddress((void**)&p_alfa,   g_alfa);
    cudaGetSymbolAddress((void**)&p_att,    g_att);
    float* p_xw0 = p_xw;
    float* p_xw1 = p_xw + (long)NROWS * 3 * HID;

    k_zero_state<<<512, 256>>>();
    k_embed<<<2048, 256>>>(x, emb);

    // input projections: [16384,300] x [1536,300]^T (+bih)
    k_gemm_nt<<<dim3(128, 12, 1), 256>>>(p_e, Wih_f, p_xw0, EDIM,
                                         EDIM, EDIM, 3*HID, 0, 0, 0,
                                         bih_f, nullptr, 0);
    k_gemm_nt<<<dim3(128, 12, 1), 256>>>(p_e, Wih_b, p_xw1, EDIM,
                                         EDIM, EDIM, 3*HID, 0, 0, 0,
                                         bih_b, nullptr, 0);

    // full recurrence in ONE persistent kernel
    k_gru_persistent<<<GRU_BLOCKS, 256, GRU_SMEM>>>(Whh_f, Whh_b, bhh_f, bhh_b);

    // masked mean pool over target span
    k_pool<<<64, 256>>>(tstart, tend);

    // tb = target . W1[:,1024:]^T + b1  (split-K 8 + reduce)
    k_gemm_target<<<dim3(1, 4, 8), 256>>>(p_target, W1 + 1024);
    k_tb_reduce<<<64, 256>>>(b1);

    // o = tanh(h . W1[:,:1024]^T + tb[b])   (M=16384,N=256,K=1024)
    k_gemm_nt<<<dim3(128, 2, 1), 256>>>(p_h, W1, p_o, 2*HID,
                                        2*HID, 4*HID, ATTD, 0, 0, 0,
                                        nullptr, p_tb, 1);

    // beta[b,k,s] = u[k] . o[b,s]           (batched NT, 256x256x256)
    k_gemm_nt<<<dim3(2, 2, 64), 256>>>(u, p_o, p_alfa, ATTD,
                                       ATTD, ATTD, SEQ,
                                       0, (long)SEQ*ATTD, (long)ATTD*SEQ,
                                       nullptr, nullptr, 2);

    // softmax over s
    k_softmax<<<2048, 256>>>();

    // result[b,k,:] = alfa[b,k,:] . h[b]    (batched NN, 256x1024x256)
    k_gemm_nn<<<dim3(2, 8, 64), 256>>>(p_alfa, p_h, p_att, SEQ,
                                       SEQ, 2*HID, 2*HID,
                                       (long)ATTD*SEQ, (long)SEQ*2*HID,
                                       (long)ATTD*2*HID);

    // final projection to 3 labels
    k_final<<<2048, 256>>>(W2, b2, out);
}